// round 4
// baseline (speedup 1.0000x reference)
#include <cuda_runtime.h>
#include <math.h>

// ---------------- problem dims ----------------
#define BB   16
#define NQ   32
#define NN   128
#define TT   352
#define DD   768
#define HH   8
#define LL   512
#define HD   96
#define FF   3072
#define NLAY 6
#define ROWS (BB*LL)          // 8192
#define TS   (NQ+NN)          // 160 text start

// ---------------- scratch (static device globals; no allocs) ----------------
__device__ float g_x[ROWS*DD];          // activations [8192,768]
__device__ float g_qkv[ROWS*3*DD];      // qkv         [8192,2304]
__device__ float g_S[BB*HH*LL*LL];      // scores/probs [128,512,512]
__device__ float g_ctx[ROWS*DD];        // attn context
__device__ float g_y[ROWS*DD];          // gemm output / gfeat tmp
__device__ float g_h[ROWS*FF];          // ffn hidden [8192,3072]

// ---------------- generic SGEMM: C = A[MxK] @ B[KxN] + bias, optional GELU ----------------
// BM=BN=128, BK=8, 256 threads, 8x8 per thread (split 4+4 tiles)
__global__ void __launch_bounds__(256, 2) sgemm_kernel(
    const float* __restrict__ A, const float* __restrict__ B,
    const float* __restrict__ bias, float* __restrict__ C,
    int M, int N, int K, int act)
{
    __shared__ float As[8][128];
    __shared__ float Bs[8][128];
    const int tid = threadIdx.x;
    const int tx = tid & 15;
    const int ty = tid >> 4;
    const int mBase = blockIdx.y * 128;
    const int nBase = blockIdx.x * 128;
    const float* Ag = A + (long)mBase * K;
    const float* Bg = B + nBase;

    const int aRow = tid >> 1;
    const int aCol = (tid & 1) << 2;
    const int bRow = tid >> 5;
    const int bCol = (tid & 31) << 2;

    float acc[8][8];
#pragma unroll
    for (int i = 0; i < 8; ++i)
#pragma unroll
        for (int j = 0; j < 8; ++j) acc[i][j] = 0.f;

    for (int k0 = 0; k0 < K; k0 += 8) {
        float4 av = *(const float4*)(Ag + (long)aRow * K + k0 + aCol);
        As[aCol + 0][aRow] = av.x;
        As[aCol + 1][aRow] = av.y;
        As[aCol + 2][aRow] = av.z;
        As[aCol + 3][aRow] = av.w;
        *(float4*)(&Bs[bRow][bCol]) = *(const float4*)(Bg + (long)(k0 + bRow) * N + bCol);
        __syncthreads();
#pragma unroll
        for (int kk = 0; kk < 8; ++kk) {
            float4 a0 = *(const float4*)(&As[kk][ty * 4]);
            float4 a1 = *(const float4*)(&As[kk][64 + ty * 4]);
            float4 b0 = *(const float4*)(&Bs[kk][tx * 4]);
            float4 b1 = *(const float4*)(&Bs[kk][64 + tx * 4]);
            float a[8] = {a0.x, a0.y, a0.z, a0.w, a1.x, a1.y, a1.z, a1.w};
            float b[8] = {b0.x, b0.y, b0.z, b0.w, b1.x, b1.y, b1.z, b1.w};
#pragma unroll
            for (int i = 0; i < 8; ++i)
#pragma unroll
                for (int j = 0; j < 8; ++j) acc[i][j] = fmaf(a[i], b[j], acc[i][j]);
        }
        __syncthreads();
    }

#pragma unroll
    for (int i = 0; i < 8; ++i) {
        int row = mBase + ((i < 4) ? (ty * 4 + i) : (64 + ty * 4 + i - 4));
        float* Crow = C + (long)row * N;
        float out[8];
#pragma unroll
        for (int j = 0; j < 8; ++j) {
            int col = nBase + ((j < 4) ? (tx * 4 + j) : (64 + tx * 4 + j - 4));
            float v = acc[i][j] + (bias ? bias[col] : 0.f);
            if (act == 1) v = 0.5f * v * (1.0f + erff(v * 0.70710678118654752f));
            out[j] = v;
        }
        *(float4*)(Crow + nBase + tx * 4)      = make_float4(out[0], out[1], out[2], out[3]);
        *(float4*)(Crow + nBase + 64 + tx * 4) = make_float4(out[4], out[5], out[6], out[7]);
    }
}

// ---------------- mask helper ----------------
__device__ __forceinline__ int keep_fn(int b, int l, const int* __restrict__ gm,
                                       const int* __restrict__ ta) {
    if (l < NQ) return 1;
    if (l < TS) return gm[b * NN + l - NQ];
    return ta[b * TT + l - TS];
}

// ---------------- attention scores: S = scale*Q@K^T + itg_bias ----------------
// grid (8 ktiles, 8 qtiles, 128 bh), 256 thr, 64x64 tile, 4x4/thread
__global__ void __launch_bounds__(256) attn_scores_kernel(
    const float* __restrict__ qkv, const int* __restrict__ gm,
    const int* __restrict__ ta, float* __restrict__ S)
{
    __shared__ float Qs[32][64];
    __shared__ float Ks[32][64];
    const int bh = blockIdx.z, b = bh >> 3, h = bh & 7;
    const int q0 = blockIdx.y * 64, k0 = blockIdx.x * 64;
    const int tid = threadIdx.x, tk = tid & 15, tq = tid >> 4;
    const float* Qg = qkv + ((long)(b * LL + q0)) * (3 * DD) + h * HD;
    const float* Kg = qkv + ((long)(b * LL + k0)) * (3 * DD) + DD + h * HD;

    float acc[4][4] = {};
    for (int d0 = 0; d0 < HD; d0 += 32) {
#pragma unroll
        for (int it = 0; it < 2; ++it) {
            int f = tid + it * 256;
            int r = f >> 3, c = (f & 7) << 2;
            float4 qv = *(const float4*)(Qg + (long)r * (3 * DD) + d0 + c);
            Qs[c + 0][r] = qv.x; Qs[c + 1][r] = qv.y; Qs[c + 2][r] = qv.z; Qs[c + 3][r] = qv.w;
            float4 kv = *(const float4*)(Kg + (long)r * (3 * DD) + d0 + c);
            Ks[c + 0][r] = kv.x; Ks[c + 1][r] = kv.y; Ks[c + 2][r] = kv.z; Ks[c + 3][r] = kv.w;
        }
        __syncthreads();
#pragma unroll
        for (int d = 0; d < 32; ++d) {
            float4 qa = *(const float4*)(&Qs[d][tq * 4]);
            float4 kb = *(const float4*)(&Ks[d][tk * 4]);
            float a[4] = {qa.x, qa.y, qa.z, qa.w};
            float bb[4] = {kb.x, kb.y, kb.z, kb.w};
#pragma unroll
            for (int i = 0; i < 4; ++i)
#pragma unroll
                for (int j = 0; j < 4; ++j) acc[i][j] = fmaf(a[i], bb[j], acc[i][j]);
        }
        __syncthreads();
    }

    const float scale = 0.10206207261596577f;  // 1/sqrt(96)
#pragma unroll
    for (int i = 0; i < 4; ++i) {
        int q = q0 + tq * 4 + i;
        int kq = keep_fn(b, q, gm, ta);
        bool qt = q >= TS;
#pragma unroll
        for (int j = 0; j < 4; ++j) {
            int k = k0 + tk * 4 + j;
            int kk = keep_fn(b, k, gm, ta);
            bool kt = k >= TS;
            bool ok = (kq != 0) && (kk != 0);
            if (qt && kt) ok = ok && (q >= k);
            if (!qt && kt) ok = false;
            S[((long)bh * LL + q) * LL + k] = acc[i][j] * scale + (ok ? 0.f : -1e9f);
        }
    }
}

// ---------------- softmax over 512-wide rows, in place ----------------
__global__ void __launch_bounds__(128) softmax_kernel(float* __restrict__ S)
{
    __shared__ float sh[4];
    long row = blockIdx.x;
    float* p = S + row * LL;
    int t = threadIdx.x, w = t >> 5, lane = t & 31;
    float4 v = ((float4*)p)[t];
    float m = fmaxf(fmaxf(v.x, v.y), fmaxf(v.z, v.w));
#pragma unroll
    for (int o = 16; o; o >>= 1) m = fmaxf(m, __shfl_xor_sync(0xffffffffu, m, o));
    if (lane == 0) sh[w] = m;
    __syncthreads();
    m = fmaxf(fmaxf(sh[0], sh[1]), fmaxf(sh[2], sh[3]));
    __syncthreads();
    v.x = __expf(v.x - m); v.y = __expf(v.y - m);
    v.z = __expf(v.z - m); v.w = __expf(v.w - m);
    float s = v.x + v.y + v.z + v.w;
#pragma unroll
    for (int o = 16; o; o >>= 1) s += __shfl_xor_sync(0xffffffffu, s, o);
    if (lane == 0) sh[w] = s;
    __syncthreads();
    s = sh[0] + sh[1] + sh[2] + sh[3];
    float inv = 1.f / s;
    v.x *= inv; v.y *= inv; v.z *= inv; v.w *= inv;
    ((float4*)p)[t] = v;
}

// ---------------- ctx = P @ V : grid (8 qtiles, 128 bh), 256 thr, 64q x 96d ----------------
__global__ void __launch_bounds__(256) attn_ctx_kernel(
    const float* __restrict__ S, const float* __restrict__ qkv, float* __restrict__ ctx)
{
    __shared__ float Ps[32][64];   // [k][q]
    __shared__ float Vs[32][96];   // [k][d]
    const int bh = blockIdx.y, b = bh >> 3, h = bh & 7;
    const int q0 = blockIdx.x * 64;
    const int tid = threadIdx.x, td = tid & 15, tq = tid >> 4;
    const float* Sg = S + ((long)bh * LL + q0) * LL;
    const float* Vg = qkv + ((long)b * LL) * (3 * DD) + 2 * DD + h * HD;

    float acc[4][6] = {};
    for (int k0 = 0; k0 < LL; k0 += 32) {
#pragma unroll
        for (int it = 0; it < 2; ++it) {
            int f = tid + it * 256;
            int r = f >> 3, c = (f & 7) << 2;
            float4 pv = *(const float4*)(Sg + (long)r * LL + k0 + c);
            Ps[c + 0][r] = pv.x; Ps[c + 1][r] = pv.y; Ps[c + 2][r] = pv.z; Ps[c + 3][r] = pv.w;
        }
#pragma unroll
        for (int it = 0; it < 3; ++it) {
            int f = tid + it * 256;
            int r = f / 24, c = (f % 24) * 4;
            *(float4*)(&Vs[r][c]) = *(const float4*)(Vg + (long)(k0 + r) * (3 * DD) + c);
        }
        __syncthreads();
#pragma unroll
        for (int kk = 0; kk < 32; ++kk) {
            float4 pa = *(const float4*)(&Ps[kk][tq * 4]);
            float pr[4] = {pa.x, pa.y, pa.z, pa.w};
            float vv[6];
#pragma unroll
            for (int j = 0; j < 6; ++j) vv[j] = Vs[kk][td * 6 + j];
#pragma unroll
            for (int i = 0; i < 4; ++i)
#pragma unroll
                for (int j = 0; j < 6; ++j) acc[i][j] = fmaf(pr[i], vv[j], acc[i][j]);
        }
        __syncthreads();
    }
#pragma unroll
    for (int i = 0; i < 4; ++i)
#pragma unroll
        for (int j = 0; j < 6; ++j)
            ctx[((long)(b * LL + q0 + tq * 4 + i)) * DD + h * HD + td * 6 + j] = acc[i][j];
}

// ---------------- residual add + LayerNorm (in-place on x) ----------------
// mode 0: y = x + pos[l] + tok ; mode 1: y = x + delta
__global__ void __launch_bounds__(256) add_ln_kernel(
    float* __restrict__ x, const float* __restrict__ delta,
    const float* __restrict__ pos, const float* __restrict__ tok,
    const float* __restrict__ g, const float* __restrict__ bt, int mode)
{
    __shared__ float sh[8];
    int row = blockIdx.x;
    int l = row & (LL - 1);
    int t = threadIdx.x, w = t >> 5, lane = t & 31;
    float* xr = x + (long)row * DD;
    float y[3];
#pragma unroll
    for (int i = 0; i < 3; ++i) {
        int d = t + i * 256;
        float v = xr[d];
        if (mode == 0) v += pos[l * DD + d] + tok[d];
        else           v += delta[(long)row * DD + d];
        y[i] = v;
    }
    float s = y[0] + y[1] + y[2];
#pragma unroll
    for (int o = 16; o; o >>= 1) s += __shfl_xor_sync(0xffffffffu, s, o);
    if (lane == 0) sh[w] = s;
    __syncthreads();
    s = sh[0] + sh[1] + sh[2] + sh[3] + sh[4] + sh[5] + sh[6] + sh[7];
    float mean = s * (1.f / DD);
    __syncthreads();
    float sq = 0.f;
#pragma unroll
    for (int i = 0; i < 3; ++i) { float d2 = y[i] - mean; sq += d2 * d2; }
#pragma unroll
    for (int o = 16; o; o >>= 1) sq += __shfl_xor_sync(0xffffffffu, sq, o);
    if (lane == 0) sh[w] = sq;
    __syncthreads();
    sq = sh[0] + sh[1] + sh[2] + sh[3] + sh[4] + sh[5] + sh[6] + sh[7];
    float rstd = rsqrtf(sq * (1.f / DD) + 1e-12f);
#pragma unroll
    for (int i = 0; i < 3; ++i) {
        int d = t + i * 256;
        xr[d] = (y[i] - mean) * rstd * g[d] + bt[d];
    }
}

// ---------------- assemble x = [queries | gfeat | text] ----------------
__global__ void __launch_bounds__(256) assemble_kernel(
    const float* __restrict__ qtok, const float* __restrict__ gfeat,
    const float* __restrict__ text, float* __restrict__ x)
{
    int row = blockIdx.x;
    int b = row >> 9, l = row & (LL - 1);
    int t = threadIdx.x;
    float* xr = x + (long)row * DD;
#pragma unroll
    for (int i = 0; i < 3; ++i) {
        int d = t + i * 256;
        float v;
        if (l < NQ)        v = qtok[l * DD + d];
        else if (l < TS)   v = gfeat[((long)(b * NN + l - NQ)) * DD + d];
        else               v = text[((long)(b * TT + l - TS)) * DD + d];
        xr[d] = v;
    }
}

// ---------------- output: text slice ----------------
__global__ void __launch_bounds__(256) output_kernel(const float* __restrict__ x,
                                                     float* __restrict__ out)
{
    long i = (long)blockIdx.x * 256 + threadIdx.x;
    const long total = (long)BB * TT * DD;
    if (i >= total) return;
    int d = (int)(i % DD);
    long r = i / DD;
    int tt = (int)(r % TT);
    int b  = (int)(r / TT);
    out[i] = x[((long)(b * LL + TS + tt)) * DD + d];
}

// ---------------- host orchestration ----------------
extern "C" void kernel_launch(void* const* d_in, const int* in_sizes, int n_in,
                              void* d_out, int out_size)
{
    const float* gnf     = (const float*)d_in[0];
    const float* text    = (const float*)d_in[1];
    const int*   ta      = (const int*)  d_in[2];
    const int*   gm      = (const int*)  d_in[3];
    const float* qtok    = (const float*)d_in[4];
    const float* gproj_w = (const float*)d_in[5];
    const float* gproj_b = (const float*)d_in[6];
    const float* pos     = (const float*)d_in[7];
    const float* tok     = (const float*)d_in[8];
    const float* eg      = (const float*)d_in[9];
    const float* eb      = (const float*)d_in[10];
    const float* qkv_w   = (const float*)d_in[11];
    const float* qkv_b   = (const float*)d_in[12];
    const float* ao_w    = (const float*)d_in[13];
    const float* ao_b    = (const float*)d_in[14];
    const float* ln1g    = (const float*)d_in[15];
    const float* ln1b    = (const float*)d_in[16];
    const float* ff1w    = (const float*)d_in[17];
    const float* ff1b    = (const float*)d_in[18];
    const float* ff2w    = (const float*)d_in[19];
    const float* ff2b    = (const float*)d_in[20];
    const float* ln2g    = (const float*)d_in[21];
    const float* ln2b    = (const float*)d_in[22];

    float *x, *qkv, *S, *ctx, *y, *hb;
    cudaGetSymbolAddress((void**)&x,   g_x);
    cudaGetSymbolAddress((void**)&qkv, g_qkv);
    cudaGetSymbolAddress((void**)&S,   g_S);
    cudaGetSymbolAddress((void**)&ctx, g_ctx);
    cudaGetSymbolAddress((void**)&y,   g_y);
    cudaGetSymbolAddress((void**)&hb,  g_h);

    // graph projection: gfeat(tmp in y) = gnf[2048,768] @ gproj_w + gproj_b
    sgemm_kernel<<<dim3(DD / 128, (BB * NN) / 128), 256>>>(gnf, gproj_w, gproj_b, y,
                                                           BB * NN, DD, DD, 0);
    // assemble x, then embedding LN
    assemble_kernel<<<ROWS, 256>>>(qtok, y, text, x);
    add_ln_kernel<<<ROWS, 256>>>(x, nullptr, pos, tok, eg, eb, 0);

    for (int i = 0; i < NLAY; ++i) {
        // qkv = x @ qkv_w[i] + qkv_b[i]
        sgemm_kernel<<<dim3((3 * DD) / 128, ROWS / 128), 256>>>(
            x, qkv_w + (long)i * DD * 3 * DD, qkv_b + (long)i * 3 * DD, qkv,
            ROWS, 3 * DD, DD, 0);
        // attention
        attn_scores_kernel<<<dim3(LL / 64, LL / 64, BB * HH), 256>>>(qkv, gm, ta, S);
        softmax_kernel<<<BB * HH * LL, 128>>>(S);
        attn_ctx_kernel<<<dim3(LL / 64, BB * HH), 256>>>(S, qkv, ctx);
        // attn output proj + residual LN
        sgemm_kernel<<<dim3(DD / 128, ROWS / 128), 256>>>(
            ctx, ao_w + (long)i * DD * DD, ao_b + (long)i * DD, y, ROWS, DD, DD, 0);
        add_ln_kernel<<<ROWS, 256>>>(x, y, nullptr, nullptr,
                                     ln1g + (long)i * DD, ln1b + (long)i * DD, 1);
        // FFN
        sgemm_kernel<<<dim3(FF / 128, ROWS / 128), 256>>>(
            x, ff1w + (long)i * DD * FF, ff1b + (long)i * FF, hb, ROWS, FF, DD, 1);
        sgemm_kernel<<<dim3(DD / 128, ROWS / 128), 256>>>(
            hb, ff2w + (long)i * FF * DD, ff2b + (long)i * DD, y, ROWS, DD, FF, 0);
        add_ln_kernel<<<ROWS, 256>>>(x, y, nullptr, nullptr,
                                     ln2g + (long)i * DD, ln2b + (long)i * DD, 1);
    }

    long total = (long)BB * TT * DD;
    output_kernel<<<(int)((total + 255) / 256), 256>>>(x, (float*)d_out);
}

// round 8
// speedup vs baseline: 2.4751x; 2.4751x over previous
#include <cuda_runtime.h>
#include <math.h>
#include <stdint.h>

// ---------------- problem dims ----------------
#define BB   16
#define NQ   32
#define NN   128
#define TT   352
#define DD   768
#define HH   8
#define LL   512
#define HD   96
#define FF   3072
#define NLAY 6
#define ROWS (BB*LL)          // 8192
#define TS   (NQ+NN)          // 160 text start

// ---------------- scratch (static device globals; no allocs) ----------------
__device__ float g_x[ROWS*DD];          // activations [8192,768]
__device__ float g_qkv[ROWS*3*DD];      // qkv         [8192,2304]
__device__ float g_S[BB*HH*LL*LL];      // scores/probs [128,512,512]
__device__ float g_ctx[ROWS*DD];        // attn context
__device__ float g_y[ROWS*DD];          // gemm output / gfeat tmp
__device__ float g_h[ROWS*FF];          // ffn hidden [8192,3072]
// transposed weights
#define WT_QKV   0L
#define WT_AO    (WT_QKV + 6L*2304*768)
#define WT_FF1   (WT_AO  + 6L*768*768)
#define WT_FF2   (WT_FF1 + 6L*3072*768)
#define WT_GP    (WT_FF2 + 6L*768*3072)
#define WT_TOTAL (WT_GP + 768L*768)
__device__ float g_wT[WT_TOTAL];

// ================= helpers =================
__device__ __forceinline__ uint32_t smem_u32(const void* p) {
    uint32_t a;
    asm("{ .reg .u64 t; cvta.to.shared.u64 t, %1; cvt.u32.u64 %0, t; }" : "=r"(a) : "l"(p));
    return a;
}
__device__ __forceinline__ uint32_t swz128(uint32_t off) { return off ^ ((off >> 3) & 0x70); }
__device__ __forceinline__ uint32_t f2tf(uint32_t bits) {
    uint32_t r; asm("cvt.rna.tf32.f32 %0, %1;" : "=r"(r) : "f"(__uint_as_float(bits))); return r;
}
#define CP_ASYNC16(s, g) \
    asm volatile("cp.async.ca.shared.global [%0], [%1], 16;" :: "r"(s), "l"(g))
#define CP_COMMIT() asm volatile("cp.async.commit_group;" ::: "memory")
#define CP_WAIT1()  asm volatile("cp.async.wait_group 1;" ::: "memory")
#define CP_WAIT0()  asm volatile("cp.async.wait_group 0;" ::: "memory")
#define LDSM_X4(r0, r1, r2, r3, addr) \
    asm volatile("ldmatrix.sync.aligned.m8n8.x4.shared.b16 {%0,%1,%2,%3}, [%4];" \
        : "=r"(r0), "=r"(r1), "=r"(r2), "=r"(r3) : "r"(addr))
#define MMA_TF32(c0, c1, c2, c3, a0, a1, a2, a3, b0, b1) \
    asm volatile("mma.sync.aligned.m16n8k8.row.col.f32.tf32.tf32.f32 " \
        "{%0,%1,%2,%3}, {%4,%5,%6,%7}, {%8,%9}, {%0,%1,%2,%3};" \
        : "+f"(c0), "+f"(c1), "+f"(c2), "+f"(c3) \
        : "r"(a0), "r"(a1), "r"(a2), "r"(a3), "r"(b0), "r"(b1))

#define GSMEM_BYTES (2 * 32768)   // 2 stages of (A 16KB + B 16KB)

// ============ tf32 mma.sync GEMM: C[M,N] = A[M,K] @ Bt[N,K]^T + bias ============
// BM=BN=128, BK=32, 256 threads (8 warps, 2x4 grid, warp tile 64x32),
// cp.async double-buffered smem, SW128 swizzle, ldmatrix fragments.
__global__ void __launch_bounds__(256) tc_gemm(
    const float* __restrict__ A, const float* __restrict__ Bt,
    const float* __restrict__ bias, float* __restrict__ C,
    int M, int N, int K, int act)
{
    extern __shared__ char smem[];
    const uint32_t sb = smem_u32(smem);
    const int tid = threadIdx.x;
    const int wid = tid >> 5, lane = tid & 31;
    const int wr = wid >> 2, wc = wid & 3;           // 2 x 4 warp grid
    const int mBase = blockIdx.y * 128, nBase = blockIdx.x * 128;

    // gmem->smem copy assignment: 4 x 16B chunks each for A and B per thread
    const int crow = tid >> 1;                // not used directly; see loop
    (void)crow;
    const int KT = K >> 5;

    float acc[4][4][4];
#pragma unroll
    for (int mi = 0; mi < 4; ++mi)
#pragma unroll
        for (int ni = 0; ni < 4; ++ni)
#pragma unroll
            for (int r = 0; r < 4; ++r) acc[mi][ni][r] = 0.f;

    // per-thread chunk coords (chunk = 16B = 4 floats); 1024 chunks per operand tile
    // chunk index g = tid + i*256 : row = g>>3, seg = g&7
    // ---- prologue: stage 0 ----
    {
        const long koff = 0;
#pragma unroll
        for (int i = 0; i < 4; ++i) {
            int g = tid + i * 256, row = g >> 3, seg = g & 7;
            uint32_t ds = swz128(row * 128 + seg * 16);
            CP_ASYNC16(sb + ds,         A  + (long)(mBase + row) * K + koff + seg * 4);
            CP_ASYNC16(sb + 16384 + ds, Bt + (long)(nBase + row) * K + koff + seg * 4);
        }
        CP_COMMIT();
    }

    // precomputed ldmatrix lane-address components
    const int a_row = (lane & 7) + ((lane >> 3) & 1) * 8;     // within m16 tile
    const int a_seg = ((lane >> 4) & 1) * 16;                 // 16B half of k8
    const int b_row = (lane & 7) + ((lane >> 4) & 1) * 8;     // within n16 pair
    const int b_seg = ((lane >> 3) & 1) * 16;

    for (int j = 0; j < KT; ++j) {
        const uint32_t As = sb + (j & 1) * 32768;
        const uint32_t Bs = As + 16384;
        if (j + 1 < KT) {
            const long koff = (long)(j + 1) * 32;
            const uint32_t st = sb + ((j + 1) & 1) * 32768;
#pragma unroll
            for (int i = 0; i < 4; ++i) {
                int g = tid + i * 256, row = g >> 3, seg = g & 7;
                uint32_t ds = swz128(row * 128 + seg * 16);
                CP_ASYNC16(st + ds,         A  + (long)(mBase + row) * K + koff + seg * 4);
                CP_ASYNC16(st + 16384 + ds, Bt + (long)(nBase + row) * K + koff + seg * 4);
            }
            CP_COMMIT();
            CP_WAIT1();
        } else {
            CP_WAIT0();
        }
        __syncthreads();

#pragma unroll
        for (int kk = 0; kk < 4; ++kk) {
            uint32_t a[4][4], b[2][4];
#pragma unroll
            for (int mi = 0; mi < 4; ++mi) {
                int row = wr * 64 + mi * 16 + a_row;
                LDSM_X4(a[mi][0], a[mi][1], a[mi][2], a[mi][3],
                        As + swz128(row * 128 + kk * 32 + a_seg));
            }
#pragma unroll
            for (int nb = 0; nb < 2; ++nb) {
                int row = wc * 32 + nb * 16 + b_row;
                LDSM_X4(b[nb][0], b[nb][1], b[nb][2], b[nb][3],
                        Bs + swz128(row * 128 + kk * 32 + b_seg));
            }
            // convert fragments to tf32 (round-to-nearest)
#pragma unroll
            for (int mi = 0; mi < 4; ++mi)
#pragma unroll
                for (int r = 0; r < 4; ++r) a[mi][r] = f2tf(a[mi][r]);
#pragma unroll
            for (int nb = 0; nb < 2; ++nb)
#pragma unroll
                for (int r = 0; r < 4; ++r) b[nb][r] = f2tf(b[nb][r]);
#pragma unroll
            for (int mi = 0; mi < 4; ++mi)
#pragma unroll
                for (int ni = 0; ni < 4; ++ni) {
                    int nb = ni >> 1, p = (ni & 1) * 2;
                    MMA_TF32(acc[mi][ni][0], acc[mi][ni][1], acc[mi][ni][2], acc[mi][ni][3],
                             a[mi][0], a[mi][1], a[mi][2], a[mi][3],
                             b[nb][p], b[nb][p + 1]);
                }
        }
        __syncthreads();
    }

    // ---- epilogue ----
    const int g4 = lane >> 2, t4 = lane & 3;
#pragma unroll
    for (int mi = 0; mi < 4; ++mi) {
#pragma unroll
        for (int r2 = 0; r2 < 2; ++r2) {
            int row = mBase + wr * 64 + mi * 16 + g4 + r2 * 8;
            float* Cp = C + (long)row * N + nBase + wc * 32;
            const float* bp = bias + nBase + wc * 32;
#pragma unroll
            for (int ni = 0; ni < 4; ++ni) {
                int col = ni * 8 + t4 * 2;
                float v0 = acc[mi][ni][r2 * 2 + 0] + bp[col];
                float v1 = acc[mi][ni][r2 * 2 + 1] + bp[col + 1];
                if (act == 1) {
                    v0 = 0.5f * v0 * (1.0f + erff(v0 * 0.70710678118654752f));
                    v1 = 0.5f * v1 * (1.0f + erff(v1 * 0.70710678118654752f));
                }
                *(float2*)(Cp + col) = make_float2(v0, v1);
            }
        }
    }
}

// ---------------- batched transpose: dst[z][C][R] = src[z][R][C]^T ----------------
__global__ void __launch_bounds__(256) transpose_kernel(
    const float* __restrict__ src, float* __restrict__ dst, int R, int C)
{
    __shared__ float t[32][33];
    long bo = (long)blockIdx.z * R * C;
    int x = blockIdx.x * 32 + threadIdx.x;
    int y = blockIdx.y * 32 + threadIdx.y;
#pragma unroll
    for (int i = 0; i < 32; i += 8)
        t[threadIdx.y + i][threadIdx.x] = src[bo + (long)(y + i) * C + x];
    __syncthreads();
    int x2 = blockIdx.y * 32 + threadIdx.x;
    int y2 = blockIdx.x * 32 + threadIdx.y;
#pragma unroll
    for (int i = 0; i < 32; i += 8)
        dst[bo + (long)(y2 + i) * R + x2] = t[threadIdx.x][threadIdx.y + i];
}

// ---------------- mask helper ----------------
__device__ __forceinline__ int keep_fn(int b, int l, const int* __restrict__ gm,
                                       const int* __restrict__ ta) {
    if (l < NQ) return 1;
    if (l < TS) return gm[b * NN + l - NQ];
    return ta[b * TT + l - TS];
}

// ---------------- attention scores: S = scale*Q@K^T + itg_bias ----------------
__global__ void __launch_bounds__(256) attn_scores_kernel(
    const float* __restrict__ qkv, const int* __restrict__ gm,
    const int* __restrict__ ta, float* __restrict__ S)
{
    __shared__ float Qs[32][64];
    __shared__ float Ks[32][64];
    const int bh = blockIdx.z, b = bh >> 3, h = bh & 7;
    const int q0 = blockIdx.y * 64, k0 = blockIdx.x * 64;
    const int tid = threadIdx.x, tk = tid & 15, tq = tid >> 4;
    const float* Qg = qkv + ((long)(b * LL + q0)) * (3 * DD) + h * HD;
    const float* Kg = qkv + ((long)(b * LL + k0)) * (3 * DD) + DD + h * HD;

    float acc[4][4] = {};
    for (int d0 = 0; d0 < HD; d0 += 32) {
#pragma unroll
        for (int it = 0; it < 2; ++it) {
            int f = tid + it * 256;
            int r = f >> 3, c = (f & 7) << 2;
            float4 qv = *(const float4*)(Qg + (long)r * (3 * DD) + d0 + c);
            Qs[c + 0][r] = qv.x; Qs[c + 1][r] = qv.y; Qs[c + 2][r] = qv.z; Qs[c + 3][r] = qv.w;
            float4 kv = *(const float4*)(Kg + (long)r * (3 * DD) + d0 + c);
            Ks[c + 0][r] = kv.x; Ks[c + 1][r] = kv.y; Ks[c + 2][r] = kv.z; Ks[c + 3][r] = kv.w;
        }
        __syncthreads();
#pragma unroll
        for (int d = 0; d < 32; ++d) {
            float4 qa = *(const float4*)(&Qs[d][tq * 4]);
            float4 kb = *(const float4*)(&Ks[d][tk * 4]);
            float a[4] = {qa.x, qa.y, qa.z, qa.w};
            float bb[4] = {kb.x, kb.y, kb.z, kb.w};
#pragma unroll
            for (int i = 0; i < 4; ++i)
#pragma unroll
                for (int j = 0; j < 4; ++j) acc[i][j] = fmaf(a[i], bb[j], acc[i][j]);
        }
        __syncthreads();
    }

    const float scale = 0.10206207261596577f;  // 1/sqrt(96)
#pragma unroll
    for (int i = 0; i < 4; ++i) {
        int q = q0 + tq * 4 + i;
        int kq = keep_fn(b, q, gm, ta);
        bool qt = q >= TS;
#pragma unroll
        for (int j = 0; j < 4; ++j) {
            int k = k0 + tk * 4 + j;
            int kk = keep_fn(b, k, gm, ta);
            bool kt = k >= TS;
            bool ok = (kq != 0) && (kk != 0);
            if (qt && kt) ok = ok && (q >= k);
            if (!qt && kt) ok = false;
            S[((long)bh * LL + q) * LL + k] = acc[i][j] * scale + (ok ? 0.f : -1e9f);
        }
    }
}

// ---------------- softmax over 512-wide rows, in place ----------------
__global__ void __launch_bounds__(128) softmax_kernel(float* __restrict__ S)
{
    __shared__ float sh[4];
    long row = blockIdx.x;
    float* p = S + row * LL;
    int t = threadIdx.x, w = t >> 5, lane = t & 31;
    float4 v = ((float4*)p)[t];
    float m = fmaxf(fmaxf(v.x, v.y), fmaxf(v.z, v.w));
#pragma unroll
    for (int o = 16; o; o >>= 1) m = fmaxf(m, __shfl_xor_sync(0xffffffffu, m, o));
    if (lane == 0) sh[w] = m;
    __syncthreads();
    m = fmaxf(fmaxf(sh[0], sh[1]), fmaxf(sh[2], sh[3]));
    __syncthreads();
    v.x = __expf(v.x - m); v.y = __expf(v.y - m);
    v.z = __expf(v.z - m); v.w = __expf(v.w - m);
    float s = v.x + v.y + v.z + v.w;
#pragma unroll
    for (int o = 16; o; o >>= 1) s += __shfl_xor_sync(0xffffffffu, s, o);
    if (lane == 0) sh[w] = s;
    __syncthreads();
    s = sh[0] + sh[1] + sh[2] + sh[3];
    float inv = 1.f / s;
    v.x *= inv; v.y *= inv; v.z *= inv; v.w *= inv;
    ((float4*)p)[t] = v;
}

// ---------------- ctx = P @ V ----------------
__global__ void __launch_bounds__(256) attn_ctx_kernel(
    const float* __restrict__ S, const float* __restrict__ qkv, float* __restrict__ ctx)
{
    __shared__ float Ps[32][64];
    __shared__ float Vs[32][96];
    const int bh = blockIdx.y, b = bh >> 3, h = bh & 7;
    const int q0 = blockIdx.x * 64;
    const int tid = threadIdx.x, td = tid & 15, tq = tid >> 4;
    const float* Sg = S + ((long)bh * LL + q0) * LL;
    const float* Vg = qkv + ((long)b * LL) * (3 * DD) + 2 * DD + h * HD;

    float acc[4][6] = {};
    for (int k0 = 0; k0 < LL; k0 += 32) {
#pragma unroll
        for (int it = 0; it < 2; ++it) {
            int f = tid + it * 256;
            int r = f >> 3, c = (f & 7) << 2;
            float4 pv = *(const float4*)(Sg + (long)r * LL + k0 + c);
            Ps[c + 0][r] = pv.x; Ps[c + 1][r] = pv.y; Ps[c + 2][r] = pv.z; Ps[c + 3][r] = pv.w;
        }
#pragma unroll
        for (int it = 0; it < 3; ++it) {
            int f = tid + it * 256;
            int r = f / 24, c = (f % 24) * 4;
            *(float4*)(&Vs[r][c]) = *(const float4*)(Vg + (long)(k0 + r) * (3 * DD) + c);
        }
        __syncthreads();
#pragma unroll
        for (int kk = 0; kk < 32; ++kk) {
            float4 pa = *(const float4*)(&Ps[kk][tq * 4]);
            float pr[4] = {pa.x, pa.y, pa.z, pa.w};
            float vv[6];
#pragma unroll
            for (int j = 0; j < 6; ++j) vv[j] = Vs[kk][td * 6 + j];
#pragma unroll
            for (int i = 0; i < 4; ++i)
#pragma unroll
                for (int j = 0; j < 6; ++j) acc[i][j] = fmaf(pr[i], vv[j], acc[i][j]);
        }
        __syncthreads();
    }
#pragma unroll
    for (int i = 0; i < 4; ++i)
#pragma unroll
        for (int j = 0; j < 6; ++j)
            ctx[((long)(b * LL + q0 + tq * 4 + i)) * DD + h * HD + td * 6 + j] = acc[i][j];
}

// ---------------- residual add + LayerNorm (in-place on x) ----------------
__global__ void __launch_bounds__(256) add_ln_kernel(
    float* __restrict__ x, const float* __restrict__ delta,
    const float* __restrict__ pos, const float* __restrict__ tok,
    const float* __restrict__ g, const float* __restrict__ bt, int mode)
{
    __shared__ float sh[8];
    int row = blockIdx.x;
    int l = row & (LL - 1);
    int t = threadIdx.x, w = t >> 5, lane = t & 31;
    float* xr = x + (long)row * DD;
    float y[3];
#pragma unroll
    for (int i = 0; i < 3; ++i) {
        int d = t + i * 256;
        float v = xr[d];
        if (mode == 0) v += pos[l * DD + d] + tok[d];
        else           v += delta[(long)row * DD + d];
        y[i] = v;
    }
    float s = y[0] + y[1] + y[2];
#pragma unroll
    for (int o = 16; o; o >>= 1) s += __shfl_xor_sync(0xffffffffu, s, o);
    if (lane == 0) sh[w] = s;
    __syncthreads();
    s = sh[0] + sh[1] + sh[2] + sh[3] + sh[4] + sh[5] + sh[6] + sh[7];
    float mean = s * (1.f / DD);
    __syncthreads();
    float sq = 0.f;
#pragma unroll
    for (int i = 0; i < 3; ++i) { float d2 = y[i] - mean; sq += d2 * d2; }
#pragma unroll
    for (int o = 16; o; o >>= 1) sq += __shfl_xor_sync(0xffffffffu, sq, o);
    if (lane == 0) sh[w] = sq;
    __syncthreads();
    sq = sh[0] + sh[1] + sh[2] + sh[3] + sh[4] + sh[5] + sh[6] + sh[7];
    float rstd = rsqrtf(sq * (1.f / DD) + 1e-12f);
#pragma unroll
    for (int i = 0; i < 3; ++i) {
        int d = t + i * 256;
        xr[d] = (y[i] - mean) * rstd * g[d] + bt[d];
    }
}

// ---------------- assemble x = [queries | gfeat | text] ----------------
__global__ void __launch_bounds__(256) assemble_kernel(
    const float* __restrict__ qtok, const float* __restrict__ gfeat,
    const float* __restrict__ text, float* __restrict__ x)
{
    int row = blockIdx.x;
    int b = row >> 9, l = row & (LL - 1);
    int t = threadIdx.x;
    float* xr = x + (long)row * DD;
#pragma unroll
    for (int i = 0; i < 3; ++i) {
        int d = t + i * 256;
        float v;
        if (l < NQ)        v = qtok[l * DD + d];
        else if (l < TS)   v = gfeat[((long)(b * NN + l - NQ)) * DD + d];
        else               v = text[((long)(b * TT + l - TS)) * DD + d];
        xr[d] = v;
    }
}

// ---------------- output: text slice ----------------
__global__ void __launch_bounds__(256) output_kernel(const float* __restrict__ x,
                                                     float* __restrict__ out)
{
    long i = (long)blockIdx.x * 256 + threadIdx.x;
    const long total = (long)BB * TT * DD;
    if (i >= total) return;
    int d = (int)(i % DD);
    long r = i / DD;
    int tt = (int)(r % TT);
    int b  = (int)(r / TT);
    out[i] = x[((long)(b * LL + TS + tt)) * DD + d];
}

// ---------------- host orchestration ----------------
extern "C" void kernel_launch(void* const* d_in, const int* in_sizes, int n_in,
                              void* d_out, int out_size)
{
    const float* gnf     = (const float*)d_in[0];
    const float* text    = (const float*)d_in[1];
    const int*   ta      = (const int*)  d_in[2];
    const int*   gm      = (const int*)  d_in[3];
    const float* qtok    = (const float*)d_in[4];
    const float* gproj_w = (const float*)d_in[5];
    const float* gproj_b = (const float*)d_in[6];
    const float* pos     = (const float*)d_in[7];
    const float* tok     = (const float*)d_in[8];
    const float* eg      = (const float*)d_in[9];
    const float* eb      = (const float*)d_in[10];
    const float* qkv_w   = (const float*)d_in[11];
    const float* qkv_b   = (const float*)d_in[12];
    const float* ao_w    = (const float*)d_in[13];
    const float* ao_b    = (const float*)d_in[14];
    const float* ln1g    = (const float*)d_in[15];
    const float* ln1b    = (const float*)d_in[16];
    const float* ff1w    = (const float*)d_in[17];
    const float* ff1b    = (const float*)d_in[18];
    const float* ff2w    = (const float*)d_in[19];
    const float* ff2b    = (const float*)d_in[20];
    const float* ln2g    = (const float*)d_in[21];
    const float* ln2b    = (const float*)d_in[22];

    float *x, *qkv, *S, *ctx, *y, *hb, *wT;
    cudaGetSymbolAddress((void**)&x,   g_x);
    cudaGetSymbolAddress((void**)&qkv, g_qkv);
    cudaGetSymbolAddress((void**)&S,   g_S);
    cudaGetSymbolAddress((void**)&ctx, g_ctx);
    cudaGetSymbolAddress((void**)&y,   g_y);
    cudaGetSymbolAddress((void**)&hb,  g_h);
    cudaGetSymbolAddress((void**)&wT,  g_wT);

    float* qkvT   = wT + WT_QKV;
    float* aoT    = wT + WT_AO;
    float* ff1T   = wT + WT_FF1;
    float* ff2T   = wT + WT_FF2;
    float* gprojT = wT + WT_GP;

    cudaFuncSetAttribute(tc_gemm, cudaFuncAttributeMaxDynamicSharedMemorySize, GSMEM_BYTES);

    dim3 tb(32, 8);
    // weight transposes into K-major B^T layouts
    transpose_kernel<<<dim3(2304/32, 768/32, 6), tb>>>(qkv_w, qkvT, 768, 2304);
    transpose_kernel<<<dim3(768/32,  768/32, 6), tb>>>(ao_w,  aoT,  768, 768);
    transpose_kernel<<<dim3(3072/32, 768/32, 6), tb>>>(ff1w,  ff1T, 768, 3072);
    transpose_kernel<<<dim3(768/32, 3072/32, 6), tb>>>(ff2w,  ff2T, 3072, 768);
    transpose_kernel<<<dim3(768/32,  768/32, 1), tb>>>(gproj_w, gprojT, 768, 768);

    // graph projection: gfeat(tmp in y) = gnf[2048,768] @ gproj_w + gproj_b
    tc_gemm<<<dim3(DD/128, (BB*NN)/128), 256, GSMEM_BYTES>>>(
        gnf, gprojT, gproj_b, y, BB*NN, DD, DD, 0);
    // assemble x, then embedding LN
    assemble_kernel<<<ROWS, 256>>>(qtok, y, text, x);
    add_ln_kernel<<<ROWS, 256>>>(x, nullptr, pos, tok, eg, eb, 0);

    for (int i = 0; i < NLAY; ++i) {
        tc_gemm<<<dim3((3*DD)/128, ROWS/128), 256, GSMEM_BYTES>>>(
            x, qkvT + (long)i * 2304 * 768, qkv_b + (long)i * 3 * DD, qkv,
            ROWS, 3*DD, DD, 0);
        attn_scores_kernel<<<dim3(LL/64, LL/64, BB*HH), 256>>>(qkv, gm, ta, S);
        softmax_kernel<<<BB*HH*LL, 128>>>(S);
        attn_ctx_kernel<<<dim3(LL/64, BB*HH), 256>>>(S, qkv, ctx);
        tc_gemm<<<dim3(DD/128, ROWS/128), 256, GSMEM_BYTES>>>(
            ctx, aoT + (long)i * 768 * 768, ao_b + (long)i * DD, y, ROWS, DD, DD, 0);
        add_ln_kernel<<<ROWS, 256>>>(x, y, nullptr, nullptr,
                                     ln1g + (long)i * DD, ln1b + (long)i * DD, 1);
        tc_gemm<<<dim3(FF/128, ROWS/128), 256, GSMEM_BYTES>>>(
            x, ff1T + (long)i * 3072 * 768, ff1b + (long)i * FF, hb, ROWS, FF, DD, 1);
        tc_gemm<<<dim3(DD/128, ROWS/128), 256, GSMEM_BYTES>>>(
            hb, ff2T + (long)i * 768 * 3072, ff2b + (long)i * DD, y, ROWS, DD, FF, 0);
        add_ln_kernel<<<ROWS, 256>>>(x, y, nullptr, nullptr,
                                     ln2g + (long)i * DD, ln2b + (long)i * DD, 1);
    }

    long total = (long)BB * TT * DD;
    output_kernel<<<(int)((total + 255) / 256), 256>>>(x, (float*)d_out);
}

// round 9
// speedup vs baseline: 2.9785x; 1.2034x over previous
#include <cuda_runtime.h>
#include <math.h>
#include <stdint.h>

// ---------------- problem dims ----------------
#define BB   16
#define NQ   32
#define NN   128
#define TT   352
#define DD   768
#define HH   8
#define LL   512
#define HD   96
#define FF   3072
#define NLAY 6
#define ROWS (BB*LL)          // 8192
#define TS   (NQ+NN)          // 160 text start

// ---------------- scratch (static device globals; no allocs) ----------------
__device__ float g_x[ROWS*DD];          // activations [8192,768]
__device__ float g_qkv[ROWS*3*DD];      // qkv         [8192,2304]
__device__ float g_S[BB*HH*LL*LL];      // scores/probs [128,512,512]
__device__ float g_ctx[ROWS*DD];        // attn context
__device__ float g_y[ROWS*DD];          // gemm output / gfeat tmp
__device__ float g_h[ROWS*FF];          // ffn hidden [8192,3072]
__device__ float g_vT[BB*HH*HD*LL];     // V transposed per head [128][96][512]
// transposed weights
#define WT_QKV   0L
#define WT_AO    (WT_QKV + 6L*2304*768)
#define WT_FF1   (WT_AO  + 6L*768*768)
#define WT_FF2   (WT_FF1 + 6L*3072*768)
#define WT_GP    (WT_FF2 + 6L*768*3072)
#define WT_TOTAL (WT_GP + 768L*768)
__device__ float g_wT[WT_TOTAL];

// ================= helpers =================
__device__ __forceinline__ uint32_t smem_u32(const void* p) {
    uint32_t a;
    asm("{ .reg .u64 t; cvta.to.shared.u64 t, %1; cvt.u32.u64 %0, t; }" : "=r"(a) : "l"(p));
    return a;
}
__device__ __forceinline__ uint32_t swz128(uint32_t off) { return off ^ ((off >> 3) & 0x70); }
__device__ __forceinline__ uint32_t f2tf(uint32_t bits) {
    uint32_t r; asm("cvt.rna.tf32.f32 %0, %1;" : "=r"(r) : "f"(__uint_as_float(bits))); return r;
}
#define CP_ASYNC16(s, g) \
    asm volatile("cp.async.ca.shared.global [%0], [%1], 16;" :: "r"(s), "l"(g))
#define CP_COMMIT() asm volatile("cp.async.commit_group;" ::: "memory")
#define CP_WAIT1()  asm volatile("cp.async.wait_group 1;" ::: "memory")
#define CP_WAIT0()  asm volatile("cp.async.wait_group 0;" ::: "memory")
#define LDSM_X4(r0, r1, r2, r3, addr) \
    asm volatile("ldmatrix.sync.aligned.m8n8.x4.shared.b16 {%0,%1,%2,%3}, [%4];" \
        : "=r"(r0), "=r"(r1), "=r"(r2), "=r"(r3) : "r"(addr))
#define MMA_TF32(c0, c1, c2, c3, a0, a1, a2, a3, b0, b1) \
    asm volatile("mma.sync.aligned.m16n8k8.row.col.f32.tf32.tf32.f32 " \
        "{%0,%1,%2,%3}, {%4,%5,%6,%7}, {%8,%9}, {%0,%1,%2,%3};" \
        : "+f"(c0), "+f"(c1), "+f"(c2), "+f"(c3) \
        : "r"(a0), "r"(a1), "r"(a2), "r"(a3), "r"(b0), "r"(b1))

#define GSMEM_BYTES  (2 * 32768)   // tc_gemm / tc_attn_scores: 2 stages of (A 16KB + B 16KB)
#define CSMEM_BYTES  (2 * 28672)   // tc_attn_ctx: 2 stages of (A 16KB + B 12KB)

// ============ tf32 mma.sync GEMM: C[M,N] = A[M,K] @ Bt[N,K]^T + bias ============
__global__ void __launch_bounds__(256) tc_gemm(
    const float* __restrict__ A, const float* __restrict__ Bt,
    const float* __restrict__ bias, float* __restrict__ C,
    int M, int N, int K, int act)
{
    extern __shared__ char smem[];
    const uint32_t sb = smem_u32(smem);
    const int tid = threadIdx.x;
    const int wid = tid >> 5, lane = tid & 31;
    const int wr = wid >> 2, wc = wid & 3;           // 2 x 4 warp grid
    const int mBase = blockIdx.y * 128, nBase = blockIdx.x * 128;
    const int KT = K >> 5;

    float acc[4][4][4];
#pragma unroll
    for (int mi = 0; mi < 4; ++mi)
#pragma unroll
        for (int ni = 0; ni < 4; ++ni)
#pragma unroll
            for (int r = 0; r < 4; ++r) acc[mi][ni][r] = 0.f;

    {
#pragma unroll
        for (int i = 0; i < 4; ++i) {
            int g = tid + i * 256, row = g >> 3, seg = g & 7;
            uint32_t ds = swz128(row * 128 + seg * 16);
            CP_ASYNC16(sb + ds,         A  + (long)(mBase + row) * K + seg * 4);
            CP_ASYNC16(sb + 16384 + ds, Bt + (long)(nBase + row) * K + seg * 4);
        }
        CP_COMMIT();
    }

    const int a_row = (lane & 7) + ((lane >> 3) & 1) * 8;
    const int a_seg = ((lane >> 4) & 1) * 16;
    const int b_row = (lane & 7) + ((lane >> 4) & 1) * 8;
    const int b_seg = ((lane >> 3) & 1) * 16;

    for (int j = 0; j < KT; ++j) {
        const uint32_t As = sb + (j & 1) * 32768;
        const uint32_t Bs = As + 16384;
        if (j + 1 < KT) {
            const long koff = (long)(j + 1) * 32;
            const uint32_t st = sb + ((j + 1) & 1) * 32768;
#pragma unroll
            for (int i = 0; i < 4; ++i) {
                int g = tid + i * 256, row = g >> 3, seg = g & 7;
                uint32_t ds = swz128(row * 128 + seg * 16);
                CP_ASYNC16(st + ds,         A  + (long)(mBase + row) * K + koff + seg * 4);
                CP_ASYNC16(st + 16384 + ds, Bt + (long)(nBase + row) * K + koff + seg * 4);
            }
            CP_COMMIT();
            CP_WAIT1();
        } else {
            CP_WAIT0();
        }
        __syncthreads();

#pragma unroll
        for (int kk = 0; kk < 4; ++kk) {
            uint32_t a[4][4], b[2][4];
#pragma unroll
            for (int mi = 0; mi < 4; ++mi) {
                int row = wr * 64 + mi * 16 + a_row;
                LDSM_X4(a[mi][0], a[mi][1], a[mi][2], a[mi][3],
                        As + swz128(row * 128 + kk * 32 + a_seg));
            }
#pragma unroll
            for (int nb = 0; nb < 2; ++nb) {
                int row = wc * 32 + nb * 16 + b_row;
                LDSM_X4(b[nb][0], b[nb][1], b[nb][2], b[nb][3],
                        Bs + swz128(row * 128 + kk * 32 + b_seg));
            }
#pragma unroll
            for (int mi = 0; mi < 4; ++mi)
#pragma unroll
                for (int r = 0; r < 4; ++r) a[mi][r] = f2tf(a[mi][r]);
#pragma unroll
            for (int nb = 0; nb < 2; ++nb)
#pragma unroll
                for (int r = 0; r < 4; ++r) b[nb][r] = f2tf(b[nb][r]);
#pragma unroll
            for (int mi = 0; mi < 4; ++mi)
#pragma unroll
                for (int ni = 0; ni < 4; ++ni) {
                    int nb = ni >> 1, p = (ni & 1) * 2;
                    MMA_TF32(acc[mi][ni][0], acc[mi][ni][1], acc[mi][ni][2], acc[mi][ni][3],
                             a[mi][0], a[mi][1], a[mi][2], a[mi][3],
                             b[nb][p], b[nb][p + 1]);
                }
        }
        __syncthreads();
    }

    const int g4 = lane >> 2, t4 = lane & 3;
#pragma unroll
    for (int mi = 0; mi < 4; ++mi) {
#pragma unroll
        for (int r2 = 0; r2 < 2; ++r2) {
            int row = mBase + wr * 64 + mi * 16 + g4 + r2 * 8;
            float* Cp = C + (long)row * N + nBase + wc * 32;
            const float* bp = bias + nBase + wc * 32;
#pragma unroll
            for (int ni = 0; ni < 4; ++ni) {
                int col = ni * 8 + t4 * 2;
                float v0 = acc[mi][ni][r2 * 2 + 0] + bp[col];
                float v1 = acc[mi][ni][r2 * 2 + 1] + bp[col + 1];
                if (act == 1) {
                    v0 = 0.5f * v0 * (1.0f + erff(v0 * 0.70710678118654752f));
                    v1 = 0.5f * v1 * (1.0f + erff(v1 * 0.70710678118654752f));
                }
                *(float2*)(Cp + col) = make_float2(v0, v1);
            }
        }
    }
}

// ---------------- mask helper ----------------
__device__ __forceinline__ int keep_fn(int b, int l, const int* __restrict__ gm,
                                       const int* __restrict__ ta) {
    if (l < NQ) return 1;
    if (l < TS) return gm[b * NN + l - NQ];
    return ta[b * TT + l - TS];
}

// ============ attention scores via mma: S = scale*Q@K^T + itg_bias ============
// grid: (4 ktile, 4 qtile, 128 bh), BM=BN=128, BK=32, K=HD=96 (3 k-tiles)
__global__ void __launch_bounds__(256) tc_attn_scores(
    const float* __restrict__ qkv, const int* __restrict__ gm,
    const int* __restrict__ ta, float* __restrict__ S)
{
    extern __shared__ char smem[];
    const uint32_t sb = smem_u32(smem);
    const int tid = threadIdx.x;
    const int wid = tid >> 5, lane = tid & 31;
    const int wr = wid >> 2, wc = wid & 3;
    const int bh = blockIdx.z, b = bh >> 3, h = bh & 7;
    const int mBase = blockIdx.y * 128, nBase = blockIdx.x * 128;

    const float* Aq = qkv + (long)(b * LL + mBase) * (3 * DD) + h * HD;        // Q
    const float* Bk = qkv + (long)(b * LL + nBase) * (3 * DD) + DD + h * HD;   // K

    float acc[4][4][4];
#pragma unroll
    for (int mi = 0; mi < 4; ++mi)
#pragma unroll
        for (int ni = 0; ni < 4; ++ni)
#pragma unroll
            for (int r = 0; r < 4; ++r) acc[mi][ni][r] = 0.f;

    {
#pragma unroll
        for (int i = 0; i < 4; ++i) {
            int g = tid + i * 256, row = g >> 3, seg = g & 7;
            uint32_t ds = swz128(row * 128 + seg * 16);
            CP_ASYNC16(sb + ds,         Aq + (long)row * (3 * DD) + seg * 4);
            CP_ASYNC16(sb + 16384 + ds, Bk + (long)row * (3 * DD) + seg * 4);
        }
        CP_COMMIT();
    }

    const int a_row = (lane & 7) + ((lane >> 3) & 1) * 8;
    const int a_seg = ((lane >> 4) & 1) * 16;
    const int b_row = (lane & 7) + ((lane >> 4) & 1) * 8;
    const int b_seg = ((lane >> 3) & 1) * 16;

#pragma unroll
    for (int j = 0; j < 3; ++j) {
        const uint32_t As = sb + (j & 1) * 32768;
        const uint32_t Bs = As + 16384;
        if (j + 1 < 3) {
            const long koff = (long)(j + 1) * 32;
            const uint32_t st = sb + ((j + 1) & 1) * 32768;
#pragma unroll
            for (int i = 0; i < 4; ++i) {
                int g = tid + i * 256, row = g >> 3, seg = g & 7;
                uint32_t ds = swz128(row * 128 + seg * 16);
                CP_ASYNC16(st + ds,         Aq + (long)row * (3 * DD) + koff + seg * 4);
                CP_ASYNC16(st + 16384 + ds, Bk + (long)row * (3 * DD) + koff + seg * 4);
            }
            CP_COMMIT();
            CP_WAIT1();
        } else {
            CP_WAIT0();
        }
        __syncthreads();

#pragma unroll
        for (int kk = 0; kk < 4; ++kk) {
            uint32_t a[4][4], b2[2][4];
#pragma unroll
            for (int mi = 0; mi < 4; ++mi) {
                int row = wr * 64 + mi * 16 + a_row;
                LDSM_X4(a[mi][0], a[mi][1], a[mi][2], a[mi][3],
                        As + swz128(row * 128 + kk * 32 + a_seg));
            }
#pragma unroll
            for (int nb = 0; nb < 2; ++nb) {
                int row = wc * 32 + nb * 16 + b_row;
                LDSM_X4(b2[nb][0], b2[nb][1], b2[nb][2], b2[nb][3],
                        Bs + swz128(row * 128 + kk * 32 + b_seg));
            }
#pragma unroll
            for (int mi = 0; mi < 4; ++mi)
#pragma unroll
                for (int r = 0; r < 4; ++r) a[mi][r] = f2tf(a[mi][r]);
#pragma unroll
            for (int nb = 0; nb < 2; ++nb)
#pragma unroll
                for (int r = 0; r < 4; ++r) b2[nb][r] = f2tf(b2[nb][r]);
#pragma unroll
            for (int mi = 0; mi < 4; ++mi)
#pragma unroll
                for (int ni = 0; ni < 4; ++ni) {
                    int nb = ni >> 1, p = (ni & 1) * 2;
                    MMA_TF32(acc[mi][ni][0], acc[mi][ni][1], acc[mi][ni][2], acc[mi][ni][3],
                             a[mi][0], a[mi][1], a[mi][2], a[mi][3],
                             b2[nb][p], b2[nb][p + 1]);
                }
        }
        __syncthreads();
    }

    // masked epilogue
    const float scale = 0.10206207261596577f;  // 1/sqrt(96)
    const int g4 = lane >> 2, t4 = lane & 3;
#pragma unroll
    for (int mi = 0; mi < 4; ++mi) {
#pragma unroll
        for (int r2 = 0; r2 < 2; ++r2) {
            int q = mBase + wr * 64 + mi * 16 + g4 + r2 * 8;
            int kq = keep_fn(b, q, gm, ta);
            bool qt = q >= TS;
            float* Sp = S + ((long)bh * LL + q) * LL + nBase + wc * 32;
#pragma unroll
            for (int ni = 0; ni < 4; ++ni) {
                int col0 = nBase + wc * 32 + ni * 8 + t4 * 2;
                float v[2];
#pragma unroll
                for (int e = 0; e < 2; ++e) {
                    int k = col0 + e;
                    int kk2 = keep_fn(b, k, gm, ta);
                    bool kt = k >= TS;
                    bool ok = (kq != 0) && (kk2 != 0);
                    if (qt && kt) ok = ok && (q >= k);
                    if (!qt && kt) ok = false;
                    v[e] = acc[mi][ni][r2 * 2 + e] * scale + (ok ? 0.f : -1e9f);
                }
                *(float2*)(Sp + ni * 8 + t4 * 2) = make_float2(v[0], v[1]);
            }
        }
    }
}

// ============ ctx = P @ V via mma: BM=128, BN=96(=HD), K=512 ============
// grid: (4 qtile, 128 bh), 256 threads, warp grid 4x2 (warp tile 32x48)
__global__ void __launch_bounds__(256) tc_attn_ctx(
    const float* __restrict__ S, const float* __restrict__ vT, float* __restrict__ ctx)
{
    extern __shared__ char smem[];
    const uint32_t sb = smem_u32(smem);
    const int tid = threadIdx.x;
    const int wid = tid >> 5, lane = tid & 31;
    const int wr = wid >> 1, wc = wid & 1;
    const int bh = blockIdx.y, b = bh >> 3, h = bh & 7;
    const int mBase = blockIdx.x * 128;

    const float* Ap = S  + ((long)bh * LL + mBase) * LL;   // P rows, stride 512
    const float* Bp = vT + (long)bh * HD * LL;             // V^T rows [96][512]

    float acc[2][6][4];
#pragma unroll
    for (int mi = 0; mi < 2; ++mi)
#pragma unroll
        for (int ni = 0; ni < 6; ++ni)
#pragma unroll
            for (int r = 0; r < 4; ++r) acc[mi][ni][r] = 0.f;

    // stage layout: A 16KB @0, B 12KB @16384; stage stride 28672
    {
#pragma unroll
        for (int i = 0; i < 4; ++i) {
            int g = tid + i * 256, row = g >> 3, seg = g & 7;
            uint32_t ds = swz128(row * 128 + seg * 16);
            CP_ASYNC16(sb + ds, Ap + (long)row * LL + seg * 4);
        }
#pragma unroll
        for (int i = 0; i < 3; ++i) {
            int g = tid + i * 256, row = g >> 3, seg = g & 7;
            uint32_t ds = swz128(row * 128 + seg * 16);
            CP_ASYNC16(sb + 16384 + ds, Bp + (long)row * LL + seg * 4);
        }
        CP_COMMIT();
    }

    const int a_row = (lane & 7) + ((lane >> 3) & 1) * 8;
    const int a_seg = ((lane >> 4) & 1) * 16;
    const int b_row = (lane & 7) + ((lane >> 4) & 1) * 8;
    const int b_seg = ((lane >> 3) & 1) * 16;

    for (int j = 0; j < 16; ++j) {
        const uint32_t As = sb + (j & 1) * 28672;
        const uint32_t Bs = As + 16384;
        if (j + 1 < 16) {
            const long koff = (long)(j + 1) * 32;
            const uint32_t st = sb + ((j + 1) & 1) * 28672;
#pragma unroll
            for (int i = 0; i < 4; ++i) {
                int g = tid + i * 256, row = g >> 3, seg = g & 7;
                uint32_t ds = swz128(row * 128 + seg * 16);
                CP_ASYNC16(st + ds, Ap + (long)row * LL + koff + seg * 4);
            }
#pragma unroll
            for (int i = 0; i < 3; ++i) {
                int g = tid + i * 256, row = g >> 3, seg = g & 7;
                uint32_t ds = swz128(row * 128 + seg * 16);
                CP_ASYNC16(st + 16384 + ds, Bp + (long)row * LL + koff + seg * 4);
            }
            CP_COMMIT();
            CP_WAIT1();
        } else {
            CP_WAIT0();
        }
        __syncthreads();

#pragma unroll
        for (int kk = 0; kk < 4; ++kk) {
            uint32_t a[2][4], b2[3][4];
#pragma unroll
            for (int mi = 0; mi < 2; ++mi) {
                int row = wr * 32 + mi * 16 + a_row;
                LDSM_X4(a[mi][0], a[mi][1], a[mi][2], a[mi][3],
                        As + swz128(row * 128 + kk * 32 + a_seg));
            }
#pragma unroll
            for (int nb = 0; nb < 3; ++nb) {
                int row = wc * 48 + nb * 16 + b_row;
                LDSM_X4(b2[nb][0], b2[nb][1], b2[nb][2], b2[nb][3],
                        Bs + swz128(row * 128 + kk * 32 + b_seg));
            }
#pragma unroll
            for (int mi = 0; mi < 2; ++mi)
#pragma unroll
                for (int r = 0; r < 4; ++r) a[mi][r] = f2tf(a[mi][r]);
#pragma unroll
            for (int nb = 0; nb < 3; ++nb)
#pragma unroll
                for (int r = 0; r < 4; ++r) b2[nb][r] = f2tf(b2[nb][r]);
#pragma unroll
            for (int mi = 0; mi < 2; ++mi)
#pragma unroll
                for (int ni = 0; ni < 6; ++ni) {
                    int nb = ni >> 1, p = (ni & 1) * 2;
                    MMA_TF32(acc[mi][ni][0], acc[mi][ni][1], acc[mi][ni][2], acc[mi][ni][3],
                             a[mi][0], a[mi][1], a[mi][2], a[mi][3],
                             b2[nb][p], b2[nb][p + 1]);
                }
        }
        __syncthreads();
    }

    const int g4 = lane >> 2, t4 = lane & 3;
#pragma unroll
    for (int mi = 0; mi < 2; ++mi) {
#pragma unroll
        for (int r2 = 0; r2 < 2; ++r2) {
            int row = mBase + wr * 32 + mi * 16 + g4 + r2 * 8;
            float* Cp = ctx + (long)(b * LL + row) * DD + h * HD + wc * 48;
#pragma unroll
            for (int ni = 0; ni < 6; ++ni) {
                int col = ni * 8 + t4 * 2;
                *(float2*)(Cp + col) =
                    make_float2(acc[mi][ni][r2 * 2 + 0], acc[mi][ni][r2 * 2 + 1]);
            }
        }
    }
}

// ---------------- V transpose per head: vT[bh][96][512] ----------------
__global__ void __launch_bounds__(256) vT_kernel(
    const float* __restrict__ qkv, float* __restrict__ vT)
{
    __shared__ float t[32][33];
    const int bh = blockIdx.z, b = bh >> 3, h = bh & 7;
    const int x = blockIdx.x * 32 + threadIdx.x;   // d (0..95)
    const int y = blockIdx.y * 32 + threadIdx.y;   // k (0..511)
    const float* src = qkv + (long)(b * LL) * (3 * DD) + 2 * DD + h * HD;
#pragma unroll
    for (int i = 0; i < 32; i += 8)
        t[threadIdx.y + i][threadIdx.x] = src[(long)(y + i) * (3 * DD) + x];
    __syncthreads();
    const int x2 = blockIdx.y * 32 + threadIdx.x;  // k
    const int y2 = blockIdx.x * 32 + threadIdx.y;  // d
    float* dst = vT + (long)bh * HD * LL;
#pragma unroll
    for (int i = 0; i < 32; i += 8)
        dst[(long)(y2 + i) * LL + x2] = t[threadIdx.x][threadIdx.y + i];
}

// ---------------- batched transpose: dst[z][C][R] = src[z][R][C]^T ----------------
__global__ void __launch_bounds__(256) transpose_kernel(
    const float* __restrict__ src, float* __restrict__ dst, int R, int C)
{
    __shared__ float t[32][33];
    long bo = (long)blockIdx.z * R * C;
    int x = blockIdx.x * 32 + threadIdx.x;
    int y = blockIdx.y * 32 + threadIdx.y;
#pragma unroll
    for (int i = 0; i < 32; i += 8)
        t[threadIdx.y + i][threadIdx.x] = src[bo + (long)(y + i) * C + x];
    __syncthreads();
    int x2 = blockIdx.y * 32 + threadIdx.x;
    int y2 = blockIdx.x * 32 + threadIdx.y;
#pragma unroll
    for (int i = 0; i < 32; i += 8)
        dst[bo + (long)(y2 + i) * R + x2] = t[threadIdx.x][threadIdx.y + i];
}

// ---------------- softmax over 512-wide rows, in place ----------------
__global__ void __launch_bounds__(128) softmax_kernel(float* __restrict__ S)
{
    __shared__ float sh[4];
    long row = blockIdx.x;
    float* p = S + row * LL;
    int t = threadIdx.x, w = t >> 5, lane = t & 31;
    float4 v = ((float4*)p)[t];
    float m = fmaxf(fmaxf(v.x, v.y), fmaxf(v.z, v.w));
#pragma unroll
    for (int o = 16; o; o >>= 1) m = fmaxf(m, __shfl_xor_sync(0xffffffffu, m, o));
    if (lane == 0) sh[w] = m;
    __syncthreads();
    m = fmaxf(fmaxf(sh[0], sh[1]), fmaxf(sh[2], sh[3]));
    __syncthreads();
    v.x = __expf(v.x - m); v.y = __expf(v.y - m);
    v.z = __expf(v.z - m); v.w = __expf(v.w - m);
    float s = v.x + v.y + v.z + v.w;
#pragma unroll
    for (int o = 16; o; o >>= 1) s += __shfl_xor_sync(0xffffffffu, s, o);
    if (lane == 0) sh[w] = s;
    __syncthreads();
    s = sh[0] + sh[1] + sh[2] + sh[3];
    float inv = 1.f / s;
    v.x *= inv; v.y *= inv; v.z *= inv; v.w *= inv;
    ((float4*)p)[t] = v;
}

// ---------------- residual add + LayerNorm (in-place on x) ----------------
__global__ void __launch_bounds__(256) add_ln_kernel(
    float* __restrict__ x, const float* __restrict__ delta,
    const float* __restrict__ pos, const float* __restrict__ tok,
    const float* __restrict__ g, const float* __restrict__ bt, int mode)
{
    __shared__ float sh[8];
    int row = blockIdx.x;
    int l = row & (LL - 1);
    int t = threadIdx.x, w = t >> 5, lane = t & 31;
    float* xr = x + (long)row * DD;
    float y[3];
#pragma unroll
    for (int i = 0; i < 3; ++i) {
        int d = t + i * 256;
        float v = xr[d];
        if (mode == 0) v += pos[l * DD + d] + tok[d];
        else           v += delta[(long)row * DD + d];
        y[i] = v;
    }
    float s = y[0] + y[1] + y[2];
#pragma unroll
    for (int o = 16; o; o >>= 1) s += __shfl_xor_sync(0xffffffffu, s, o);
    if (lane == 0) sh[w] = s;
    __syncthreads();
    s = sh[0] + sh[1] + sh[2] + sh[3] + sh[4] + sh[5] + sh[6] + sh[7];
    float mean = s * (1.f / DD);
    __syncthreads();
    float sq = 0.f;
#pragma unroll
    for (int i = 0; i < 3; ++i) { float d2 = y[i] - mean; sq += d2 * d2; }
#pragma unroll
    for (int o = 16; o; o >>= 1) sq += __shfl_xor_sync(0xffffffffu, sq, o);
    if (lane == 0) sh[w] = sq;
    __syncthreads();
    sq = sh[0] + sh[1] + sh[2] + sh[3] + sh[4] + sh[5] + sh[6] + sh[7];
    float rstd = rsqrtf(sq * (1.f / DD) + 1e-12f);
#pragma unroll
    for (int i = 0; i < 3; ++i) {
        int d = t + i * 256;
        xr[d] = (y[i] - mean) * rstd * g[d] + bt[d];
    }
}

// ---------------- assemble x = [queries | gfeat | text] ----------------
__global__ void __launch_bounds__(256) assemble_kernel(
    const float* __restrict__ qtok, const float* __restrict__ gfeat,
    const float* __restrict__ text, float* __restrict__ x)
{
    int row = blockIdx.x;
    int b = row >> 9, l = row & (LL - 1);
    int t = threadIdx.x;
    float* xr = x + (long)row * DD;
#pragma unroll
    for (int i = 0; i < 3; ++i) {
        int d = t + i * 256;
        float v;
        if (l < NQ)        v = qtok[l * DD + d];
        else if (l < TS)   v = gfeat[((long)(b * NN + l - NQ)) * DD + d];
        else               v = text[((long)(b * TT + l - TS)) * DD + d];
        xr[d] = v;
    }
}

// ---------------- output: text slice ----------------
__global__ void __launch_bounds__(256) output_kernel(const float* __restrict__ x,
                                                     float* __restrict__ out)
{
    long i = (long)blockIdx.x * 256 + threadIdx.x;
    const long total = (long)BB * TT * DD;
    if (i >= total) return;
    int d = (int)(i % DD);
    long r = i / DD;
    int tt = (int)(r % TT);
    int b  = (int)(r / TT);
    out[i] = x[((long)(b * LL + TS + tt)) * DD + d];
}

// ---------------- host orchestration ----------------
extern "C" void kernel_launch(void* const* d_in, const int* in_sizes, int n_in,
                              void* d_out, int out_size)
{
    const float* gnf     = (const float*)d_in[0];
    const float* text    = (const float*)d_in[1];
    const int*   ta      = (const int*)  d_in[2];
    const int*   gm      = (const int*)  d_in[3];
    const float* qtok    = (const float*)d_in[4];
    const float* gproj_w = (const float*)d_in[5];
    const float* gproj_b = (const float*)d_in[6];
    const float* pos     = (const float*)d_in[7];
    const float* tok     = (const float*)d_in[8];
    const float* eg      = (const float*)d_in[9];
    const float* eb      = (const float*)d_in[10];
    const float* qkv_w   = (const float*)d_in[11];
    const float* qkv_b   = (const float*)d_in[12];
    const float* ao_w    = (const float*)d_in[13];
    const float* ao_b    = (const float*)d_in[14];
    const float* ln1g    = (const float*)d_in[15];
    const float* ln1b    = (const float*)d_in[16];
    const float* ff1w    = (const float*)d_in[17];
    const float* ff1b    = (const float*)d_in[18];
    const float* ff2w    = (const float*)d_in[19];
    const float* ff2b    = (const float*)d_in[20];
    const float* ln2g    = (const float*)d_in[21];
    const float* ln2b    = (const float*)d_in[22];

    float *x, *qkv, *S, *ctx, *y, *hb, *wT, *vT;
    cudaGetSymbolAddress((void**)&x,   g_x);
    cudaGetSymbolAddress((void**)&qkv, g_qkv);
    cudaGetSymbolAddress((void**)&S,   g_S);
    cudaGetSymbolAddress((void**)&ctx, g_ctx);
    cudaGetSymbolAddress((void**)&y,   g_y);
    cudaGetSymbolAddress((void**)&hb,  g_h);
    cudaGetSymbolAddress((void**)&wT,  g_wT);
    cudaGetSymbolAddress((void**)&vT,  g_vT);

    float* qkvT   = wT + WT_QKV;
    float* aoT    = wT + WT_AO;
    float* ff1T   = wT + WT_FF1;
    float* ff2T   = wT + WT_FF2;
    float* gprojT = wT + WT_GP;

    cudaFuncSetAttribute(tc_gemm, cudaFuncAttributeMaxDynamicSharedMemorySize, GSMEM_BYTES);
    cudaFuncSetAttribute(tc_attn_scores, cudaFuncAttributeMaxDynamicSharedMemorySize, GSMEM_BYTES);
    cudaFuncSetAttribute(tc_attn_ctx, cudaFuncAttributeMaxDynamicSharedMemorySize, CSMEM_BYTES);

    dim3 tb(32, 8);
    // weight transposes into K-major B^T layouts
    transpose_kernel<<<dim3(2304/32, 768/32, 6), tb>>>(qkv_w, qkvT, 768, 2304);
    transpose_kernel<<<dim3(768/32,  768/32, 6), tb>>>(ao_w,  aoT,  768, 768);
    transpose_kernel<<<dim3(3072/32, 768/32, 6), tb>>>(ff1w,  ff1T, 768, 3072);
    transpose_kernel<<<dim3(768/32, 3072/32, 6), tb>>>(ff2w,  ff2T, 3072, 768);
    transpose_kernel<<<dim3(768/32,  768/32, 1), tb>>>(gproj_w, gprojT, 768, 768);

    // graph projection: gfeat(tmp in y) = gnf[2048,768] @ gproj_w + gproj_b
    tc_gemm<<<dim3(DD/128, (BB*NN)/128), 256, GSMEM_BYTES>>>(
        gnf, gprojT, gproj_b, y, BB*NN, DD, DD, 0);
    // assemble x, then embedding LN
    assemble_kernel<<<ROWS, 256>>>(qtok, y, text, x);
    add_ln_kernel<<<ROWS, 256>>>(x, nullptr, pos, tok, eg, eb, 0);

    for (int i = 0; i < NLAY; ++i) {
        tc_gemm<<<dim3((3*DD)/128, ROWS/128), 256, GSMEM_BYTES>>>(
            x, qkvT + (long)i * 2304 * 768, qkv_b + (long)i * 3 * DD, qkv,
            ROWS, 3*DD, DD, 0);
        // attention: tensor-core scores + softmax + tensor-core P@V
        tc_attn_scores<<<dim3(LL/128, LL/128, BB*HH), 256, GSMEM_BYTES>>>(qkv, gm, ta, S);
        softmax_kernel<<<BB*HH*LL, 128>>>(S);
        vT_kernel<<<dim3(HD/32, LL/32, BB*HH), tb>>>(qkv, vT);
        tc_attn_ctx<<<dim3(LL/128, BB*HH), 256, CSMEM_BYTES>>>(S, vT, ctx);
        tc_gemm<<<dim3(DD/128, ROWS/128), 256, GSMEM_BYTES>>>(
            ctx, aoT + (long)i * 768 * 768, ao_b + (long)i * DD, y, ROWS, DD, DD, 0);
        add_ln_kernel<<<ROWS, 256>>>(x, y, nullptr, nullptr,
                                     ln1g + (long)i * DD, ln1b + (long)i * DD, 1);
        tc_gemm<<<dim3(FF/128, ROWS/128), 256, GSMEM_BYTES>>>(
            x, ff1T + (long)i * 3072 * 768, ff1b + (long)i * FF, hb, ROWS, FF, DD, 1);
        tc_gemm<<<dim3(DD/128, ROWS/128), 256, GSMEM_BYTES>>>(
            hb, ff2T + (long)i * 768 * 3072, ff2b + (long)i * DD, y, ROWS, DD, FF, 0);
        add_ln_kernel<<<ROWS, 256>>>(x, y, nullptr, nullptr,
                                     ln2g + (long)i * DD, ln2b + (long)i * DD, 1);
    }

    long total = (long)BB * TT * DD;
    output_kernel<<<(int)((total + 255) / 256), 256>>>(x, (float*)d_out);
}

// round 10
// speedup vs baseline: 3.0932x; 1.0385x over previous
#include <cuda_runtime.h>
#include <math.h>
#include <stdint.h>

// ---------------- problem dims ----------------
#define BB   16
#define NQ   32
#define NN   128
#define TT   352
#define DD   768
#define HH   8
#define LL   512
#define HD   96
#define FF   3072
#define NLAY 6
#define ROWS (BB*LL)          // 8192
#define TS   (NQ+NN)          // 160 text start

// ---------------- scratch (static device globals; no allocs) ----------------
__device__ float g_x[ROWS*DD];          // activations [8192,768]
__device__ float g_qkv[ROWS*3*DD];      // qkv         [8192,2304]
__device__ float g_S[BB*HH*LL*LL];      // unnormalized probs [128,512,512]
__device__ float g_ctx[ROWS*DD];        // attn context
__device__ float g_y[ROWS*DD];          // gemm output / gfeat tmp
__device__ float g_h[ROWS*FF];          // ffn hidden [8192,3072]
__device__ float g_vT[BB*HH*HD*LL];     // V transposed per head [128][96][512]
__device__ float g_rsum[BB*HH*LL];      // 1/rowsum per (bh, q)
// transposed weights
#define WT_QKV   0L
#define WT_AO    (WT_QKV + 6L*2304*768)
#define WT_FF1   (WT_AO  + 6L*768*768)
#define WT_FF2   (WT_FF1 + 6L*3072*768)
#define WT_GP    (WT_FF2 + 6L*768*3072)
#define WT_TOTAL (WT_GP + 768L*768)
__device__ float g_wT[WT_TOTAL];

// ================= helpers =================
__device__ __forceinline__ uint32_t smem_u32(const void* p) {
    uint32_t a;
    asm("{ .reg .u64 t; cvta.to.shared.u64 t, %1; cvt.u32.u64 %0, t; }" : "=r"(a) : "l"(p));
    return a;
}
__device__ __forceinline__ uint32_t swz128(uint32_t off) { return off ^ ((off >> 3) & 0x70); }
__device__ __forceinline__ uint32_t f2tf(uint32_t bits) {
    uint32_t r; asm("cvt.rna.tf32.f32 %0, %1;" : "=r"(r) : "f"(__uint_as_float(bits))); return r;
}
#define CP_ASYNC16(s, g) \
    asm volatile("cp.async.ca.shared.global [%0], [%1], 16;" :: "r"(s), "l"(g))
#define CP_COMMIT() asm volatile("cp.async.commit_group;" ::: "memory")
#define CP_WAIT1()  asm volatile("cp.async.wait_group 1;" ::: "memory")
#define CP_WAIT0()  asm volatile("cp.async.wait_group 0;" ::: "memory")
#define LDSM_X4(r0, r1, r2, r3, addr) \
    asm volatile("ldmatrix.sync.aligned.m8n8.x4.shared.b16 {%0,%1,%2,%3}, [%4];" \
        : "=r"(r0), "=r"(r1), "=r"(r2), "=r"(r3) : "r"(addr))
#define MMA_TF32(c0, c1, c2, c3, a0, a1, a2, a3, b0, b1) \
    asm volatile("mma.sync.aligned.m16n8k8.row.col.f32.tf32.tf32.f32 " \
        "{%0,%1,%2,%3}, {%4,%5,%6,%7}, {%8,%9}, {%0,%1,%2,%3};" \
        : "+f"(c0), "+f"(c1), "+f"(c2), "+f"(c3) \
        : "r"(a0), "r"(a1), "r"(a2), "r"(a3), "r"(b0), "r"(b1))

#define GSTAGE 32768
#define GSMEM_BYTES (3 * GSTAGE)     // tc_gemm: 3 stages of (A 16KB + B 16KB)
#define SSMEM_BYTES (6 * 16384)      // scores: 3 Q panels + 3 K ring slots
#define CSTAGE 28672
#define CSMEM_BYTES (3 * CSTAGE)     // ctx: 3 stages of (A 16KB + B 12KB)

// ============ tf32 mma.sync GEMM: C[M,N] = A[M,K] @ Bt[N,K]^T + bias ============
// BM=BN=128, BK=32, 256 threads (8 warps, 2x4), 3-stage cp.async pipeline.
__global__ void __launch_bounds__(256) tc_gemm(
    const float* __restrict__ A, const float* __restrict__ Bt,
    const float* __restrict__ bias, float* __restrict__ C,
    int M, int N, int K, int act)
{
    extern __shared__ char smem[];
    const uint32_t sb = smem_u32(smem);
    const int tid = threadIdx.x;
    const int wid = tid >> 5, lane = tid & 31;
    const int wr = wid >> 2, wc = wid & 3;
    const int mBase = blockIdx.y * 128, nBase = blockIdx.x * 128;
    const int KT = K >> 5;

    float acc[4][4][4];
#pragma unroll
    for (int mi = 0; mi < 4; ++mi)
#pragma unroll
        for (int ni = 0; ni < 4; ++ni)
#pragma unroll
            for (int r = 0; r < 4; ++r) acc[mi][ni][r] = 0.f;

    // prologue: stages 0 and 1
#pragma unroll
    for (int s = 0; s < 2; ++s) {
        const long koff = (long)s * 32;
        const uint32_t st = sb + s * GSTAGE;
#pragma unroll
        for (int i = 0; i < 4; ++i) {
            int g = tid + i * 256, row = g >> 3, seg = g & 7;
            uint32_t ds = swz128(row * 128 + seg * 16);
            CP_ASYNC16(st + ds,         A  + (long)(mBase + row) * K + koff + seg * 4);
            CP_ASYNC16(st + 16384 + ds, Bt + (long)(nBase + row) * K + koff + seg * 4);
        }
        CP_COMMIT();
    }

    const int a_row = (lane & 7) + ((lane >> 3) & 1) * 8;
    const int a_seg = ((lane >> 4) & 1) * 16;
    const int b_row = (lane & 7) + ((lane >> 4) & 1) * 8;
    const int b_seg = ((lane >> 3) & 1) * 16;

    for (int j = 0; j < KT; ++j) {
        if (j == KT - 1) { CP_WAIT0(); } else { CP_WAIT1(); }
        __syncthreads();
        if (j + 2 < KT) {
            const long koff = (long)(j + 2) * 32;
            const uint32_t st = sb + ((j + 2) % 3) * GSTAGE;
#pragma unroll
            for (int i = 0; i < 4; ++i) {
                int g = tid + i * 256, row = g >> 3, seg = g & 7;
                uint32_t ds = swz128(row * 128 + seg * 16);
                CP_ASYNC16(st + ds,         A  + (long)(mBase + row) * K + koff + seg * 4);
                CP_ASYNC16(st + 16384 + ds, Bt + (long)(nBase + row) * K + koff + seg * 4);
            }
            CP_COMMIT();
        }
        const uint32_t As = sb + (j % 3) * GSTAGE;
        const uint32_t Bs = As + 16384;
#pragma unroll
        for (int kk = 0; kk < 4; ++kk) {
            uint32_t a[4][4], b[2][4];
#pragma unroll
            for (int mi = 0; mi < 4; ++mi) {
                int row = wr * 64 + mi * 16 + a_row;
                LDSM_X4(a[mi][0], a[mi][1], a[mi][2], a[mi][3],
                        As + swz128(row * 128 + kk * 32 + a_seg));
            }
#pragma unroll
            for (int nb = 0; nb < 2; ++nb) {
                int row = wc * 32 + nb * 16 + b_row;
                LDSM_X4(b[nb][0], b[nb][1], b[nb][2], b[nb][3],
                        Bs + swz128(row * 128 + kk * 32 + b_seg));
            }
#pragma unroll
            for (int mi = 0; mi < 4; ++mi)
#pragma unroll
                for (int r = 0; r < 4; ++r) a[mi][r] = f2tf(a[mi][r]);
#pragma unroll
            for (int nb = 0; nb < 2; ++nb)
#pragma unroll
                for (int r = 0; r < 4; ++r) b[nb][r] = f2tf(b[nb][r]);
#pragma unroll
            for (int mi = 0; mi < 4; ++mi)
#pragma unroll
                for (int ni = 0; ni < 4; ++ni) {
                    int nb = ni >> 1, p = (ni & 1) * 2;
                    MMA_TF32(acc[mi][ni][0], acc[mi][ni][1], acc[mi][ni][2], acc[mi][ni][3],
                             a[mi][0], a[mi][1], a[mi][2], a[mi][3],
                             b[nb][p], b[nb][p + 1]);
                }
        }
    }

    const int g4 = lane >> 2, t4 = lane & 3;
#pragma unroll
    for (int mi = 0; mi < 4; ++mi) {
#pragma unroll
        for (int r2 = 0; r2 < 2; ++r2) {
            int row = mBase + wr * 64 + mi * 16 + g4 + r2 * 8;
            float* Cp = C + (long)row * N + nBase + wc * 32;
            const float* bp = bias + nBase + wc * 32;
#pragma unroll
            for (int ni = 0; ni < 4; ++ni) {
                int col = ni * 8 + t4 * 2;
                float v0 = acc[mi][ni][r2 * 2 + 0] + bp[col];
                float v1 = acc[mi][ni][r2 * 2 + 1] + bp[col + 1];
                if (act == 1) {
                    v0 = 0.5f * v0 * (1.0f + erff(v0 * 0.70710678118654752f));
                    v1 = 0.5f * v1 * (1.0f + erff(v1 * 0.70710678118654752f));
                }
                *(float2*)(Cp + col) = make_float2(v0, v1);
            }
        }
    }
}

// ---------------- mask helper ----------------
__device__ __forceinline__ int keep_fn(int b, int l, const int* __restrict__ gm,
                                       const int* __restrict__ ta) {
    if (l < NQ) return 1;
    if (l < TS) return gm[b * NN + l - NQ];
    return ta[b * TT + l - TS];
}

// ============ fused scores + exp: P = exp(scale*Q@K^T masked), rsum = 1/rowsum ============
// grid (4 qtiles, 128 bh), 256 threads. Q resident (3 panels), K 3-slot ring,
// loops all 4 key-tiles; max-free softmax (masked -> 0).
__global__ void __launch_bounds__(256) tc_attn_scores(
    const float* __restrict__ qkv, const int* __restrict__ gm,
    const int* __restrict__ ta, float* __restrict__ S, float* __restrict__ rsum)
{
    extern __shared__ char smem[];
    const uint32_t sb = smem_u32(smem);
    const int tid = threadIdx.x;
    const int wid = tid >> 5, lane = tid & 31;
    const int wr = wid >> 2, wc = wid & 3;
    const int bh = blockIdx.y, b = bh >> 3, h = bh & 7;
    const int mBase = blockIdx.x * 128;

    const float* Aq  = qkv + (long)(b * LL + mBase) * (3 * DD) + h * HD;   // Q rows
    const float* Bk0 = qkv + (long)(b * LL) * (3 * DD) + DD + h * HD;      // K rows (all 512)

    // prologue: Q panels 0..2 as one group
#pragma unroll
    for (int p = 0; p < 3; ++p) {
#pragma unroll
        for (int i = 0; i < 4; ++i) {
            int g = tid + i * 256, row = g >> 3, seg = g & 7;
            uint32_t ds = swz128(row * 128 + seg * 16);
            CP_ASYNC16(sb + p * 16384 + ds, Aq + (long)row * (3 * DD) + p * 32 + seg * 4);
        }
    }
    CP_COMMIT();
    // K panels t=0,1 (t = nt*3 + kp)
#pragma unroll
    for (int t = 0; t < 2; ++t) {
        int nt = t / 3, kp = t % 3;
#pragma unroll
        for (int i = 0; i < 4; ++i) {
            int g = tid + i * 256, row = g >> 3, seg = g & 7;
            uint32_t ds = swz128(row * 128 + seg * 16);
            CP_ASYNC16(sb + 49152 + (t % 3) * 16384 + ds,
                       Bk0 + (long)(nt * 128 + row) * (3 * DD) + kp * 32 + seg * 4);
        }
        CP_COMMIT();
    }

    const int a_row = (lane & 7) + ((lane >> 3) & 1) * 8;
    const int a_seg = ((lane >> 4) & 1) * 16;
    const int b_row = (lane & 7) + ((lane >> 4) & 1) * 8;
    const int b_seg = ((lane >> 3) & 1) * 16;
    const int g4 = lane >> 2, t4 = lane & 3;
    const float scale = 0.10206207261596577f;  // 1/sqrt(96)

    float acc[4][4][4];
#pragma unroll
    for (int mi = 0; mi < 4; ++mi)
#pragma unroll
        for (int ni = 0; ni < 4; ++ni)
#pragma unroll
            for (int r = 0; r < 4; ++r) acc[mi][ni][r] = 0.f;
    float rowsum[4][2];
#pragma unroll
    for (int mi = 0; mi < 4; ++mi) { rowsum[mi][0] = 0.f; rowsum[mi][1] = 0.f; }

    for (int t = 0; t < 12; ++t) {
        if (t == 11) { CP_WAIT0(); } else { CP_WAIT1(); }
        __syncthreads();
        if (t + 2 < 12) {
            int tn = t + 2, nt = tn / 3, kp = tn % 3;
#pragma unroll
            for (int i = 0; i < 4; ++i) {
                int g = tid + i * 256, row = g >> 3, seg = g & 7;
                uint32_t ds = swz128(row * 128 + seg * 16);
                CP_ASYNC16(sb + 49152 + (tn % 3) * 16384 + ds,
                           Bk0 + (long)(nt * 128 + row) * (3 * DD) + kp * 32 + seg * 4);
            }
            CP_COMMIT();
        }
        const uint32_t As = sb + (t % 3) * 16384;          // Q panel kp = t%3
        const uint32_t Bs = sb + 49152 + (t % 3) * 16384;  // K ring slot
#pragma unroll
        for (int kk = 0; kk < 4; ++kk) {
            uint32_t a[4][4], b2[2][4];
#pragma unroll
            for (int mi = 0; mi < 4; ++mi) {
                int row = wr * 64 + mi * 16 + a_row;
                LDSM_X4(a[mi][0], a[mi][1], a[mi][2], a[mi][3],
                        As + swz128(row * 128 + kk * 32 + a_seg));
            }
#pragma unroll
            for (int nb = 0; nb < 2; ++nb) {
                int row = wc * 32 + nb * 16 + b_row;
                LDSM_X4(b2[nb][0], b2[nb][1], b2[nb][2], b2[nb][3],
                        Bs + swz128(row * 128 + kk * 32 + b_seg));
            }
#pragma unroll
            for (int mi = 0; mi < 4; ++mi)
#pragma unroll
                for (int r = 0; r < 4; ++r) a[mi][r] = f2tf(a[mi][r]);
#pragma unroll
            for (int nb = 0; nb < 2; ++nb)
#pragma unroll
                for (int r = 0; r < 4; ++r) b2[nb][r] = f2tf(b2[nb][r]);
#pragma unroll
            for (int mi = 0; mi < 4; ++mi)
#pragma unroll
                for (int ni = 0; ni < 4; ++ni) {
                    int nb = ni >> 1, p = (ni & 1) * 2;
                    MMA_TF32(acc[mi][ni][0], acc[mi][ni][1], acc[mi][ni][2], acc[mi][ni][3],
                             a[mi][0], a[mi][1], a[mi][2], a[mi][3],
                             b2[nb][p], b2[nb][p + 1]);
                }
        }

        if (t % 3 == 2) {
            // epilogue for key-tile nt: mask, exp, store P, accumulate row sums
            const int nBase = (t / 3) * 128;
#pragma unroll
            for (int mi = 0; mi < 4; ++mi) {
#pragma unroll
                for (int r2 = 0; r2 < 2; ++r2) {
                    int q = mBase + wr * 64 + mi * 16 + g4 + r2 * 8;
                    int kq = keep_fn(b, q, gm, ta);
                    bool qt = q >= TS;
                    float* Sp = S + ((long)bh * LL + q) * LL;
                    float part = 0.f;
#pragma unroll
                    for (int ni = 0; ni < 4; ++ni) {
                        int col0 = nBase + wc * 32 + ni * 8 + t4 * 2;
                        float v[2];
#pragma unroll
                        for (int e = 0; e < 2; ++e) {
                            int k = col0 + e;
                            int kk2 = keep_fn(b, k, gm, ta);
                            bool kt = k >= TS;
                            bool ok = (kq != 0) && (kk2 != 0);
                            if (qt && kt) ok = ok && (q >= k);
                            if (!qt && kt) ok = false;
                            v[e] = ok ? __expf(acc[mi][ni][r2 * 2 + e] * scale) : 0.f;
                        }
                        part += v[0] + v[1];
                        *(float2*)(Sp + col0) = make_float2(v[0], v[1]);
                    }
                    rowsum[mi][r2] += part;
#pragma unroll
                    for (int ni = 0; ni < 4; ++ni) {
                        acc[mi][ni][r2 * 2 + 0] = 0.f;
                        acc[mi][ni][r2 * 2 + 1] = 0.f;
                    }
                }
            }
        }
    }

    // reduce row sums: t4 lanes (shfl) then wc warps (smem)
    __syncthreads();
    float* ssum = (float*)smem;   // [128][4]
#pragma unroll
    for (int mi = 0; mi < 4; ++mi)
#pragma unroll
        for (int r2 = 0; r2 < 2; ++r2) {
            float v = rowsum[mi][r2];
            v += __shfl_xor_sync(0xffffffffu, v, 1);
            v += __shfl_xor_sync(0xffffffffu, v, 2);
            if (t4 == 0) ssum[(wr * 64 + mi * 16 + g4 + r2 * 8) * 4 + wc] = v;
        }
    __syncthreads();
    if (tid < 128) {
        float tot = ssum[tid * 4] + ssum[tid * 4 + 1] + ssum[tid * 4 + 2] + ssum[tid * 4 + 3];
        rsum[(long)bh * LL + mBase + tid] = 1.f / tot;
    }
}

// ============ ctx = P @ V (unnormalized) * inv_rowsum: BM=128, BN=96, K=512 ============
// grid: (4 qtile, 128 bh), 256 threads, warp grid 4x2, 3-stage pipeline.
__global__ void __launch_bounds__(256) tc_attn_ctx(
    const float* __restrict__ S, const float* __restrict__ vT,
    const float* __restrict__ rsum, float* __restrict__ ctx)
{
    extern __shared__ char smem[];
    const uint32_t sb = smem_u32(smem);
    const int tid = threadIdx.x;
    const int wid = tid >> 5, lane = tid & 31;
    const int wr = wid >> 1, wc = wid & 1;
    const int bh = blockIdx.y, b = bh >> 3, h = bh & 7;
    const int mBase = blockIdx.x * 128;

    const float* Ap = S  + ((long)bh * LL + mBase) * LL;
    const float* Bp = vT + (long)bh * HD * LL;

    float acc[2][6][4];
#pragma unroll
    for (int mi = 0; mi < 2; ++mi)
#pragma unroll
        for (int ni = 0; ni < 6; ++ni)
#pragma unroll
            for (int r = 0; r < 4; ++r) acc[mi][ni][r] = 0.f;

#pragma unroll
    for (int s = 0; s < 2; ++s) {
        const long koff = (long)s * 32;
        const uint32_t st = sb + s * CSTAGE;
#pragma unroll
        for (int i = 0; i < 4; ++i) {
            int g = tid + i * 256, row = g >> 3, seg = g & 7;
            uint32_t ds = swz128(row * 128 + seg * 16);
            CP_ASYNC16(st + ds, Ap + (long)row * LL + koff + seg * 4);
        }
#pragma unroll
        for (int i = 0; i < 3; ++i) {
            int g = tid + i * 256, row = g >> 3, seg = g & 7;
            uint32_t ds = swz128(row * 128 + seg * 16);
            CP_ASYNC16(st + 16384 + ds, Bp + (long)row * LL + koff + seg * 4);
        }
        CP_COMMIT();
    }

    const int a_row = (lane & 7) + ((lane >> 3) & 1) * 8;
    const int a_seg = ((lane >> 4) & 1) * 16;
    const int b_row = (lane & 7) + ((lane >> 4) & 1) * 8;
    const int b_seg = ((lane >> 3) & 1) * 16;

    for (int j = 0; j < 16; ++j) {
        if (j == 15) { CP_WAIT0(); } else { CP_WAIT1(); }
        __syncthreads();
        if (j + 2 < 16) {
            const long koff = (long)(j + 2) * 32;
            const uint32_t st = sb + ((j + 2) % 3) * CSTAGE;
#pragma unroll
            for (int i = 0; i < 4; ++i) {
                int g = tid + i * 256, row = g >> 3, seg = g & 7;
                uint32_t ds = swz128(row * 128 + seg * 16);
                CP_ASYNC16(st + ds, Ap + (long)row * LL + koff + seg * 4);
            }
#pragma unroll
            for (int i = 0; i < 3; ++i) {
                int g = tid + i * 256, row = g >> 3, seg = g & 7;
                uint32_t ds = swz128(row * 128 + seg * 16);
                CP_ASYNC16(st + 16384 + ds, Bp + (long)row * LL + koff + seg * 4);
            }
            CP_COMMIT();
        }
        const uint32_t As = sb + (j % 3) * CSTAGE;
        const uint32_t Bs = As + 16384;
#pragma unroll
        for (int kk = 0; kk < 4; ++kk) {
            uint32_t a[2][4], b2[3][4];
#pragma unroll
            for (int mi = 0; mi < 2; ++mi) {
                int row = wr * 32 + mi * 16 + a_row;
                LDSM_X4(a[mi][0], a[mi][1], a[mi][2], a[mi][3],
                        As + swz128(row * 128 + kk * 32 + a_seg));
            }
#pragma unroll
            for (int nb = 0; nb < 3; ++nb) {
                int row = wc * 48 + nb * 16 + b_row;
                LDSM_X4(b2[nb][0], b2[nb][1], b2[nb][2], b2[nb][3],
                        Bs + swz128(row * 128 + kk * 32 + b_seg));
            }
#pragma unroll
            for (int mi = 0; mi < 2; ++mi)
#pragma unroll
                for (int r = 0; r < 4; ++r) a[mi][r] = f2tf(a[mi][r]);
#pragma unroll
            for (int nb = 0; nb < 3; ++nb)
#pragma unroll
                for (int r = 0; r < 4; ++r) b2[nb][r] = f2tf(b2[nb][r]);
#pragma unroll
            for (int mi = 0; mi < 2; ++mi)
#pragma unroll
                for (int ni = 0; ni < 6; ++ni) {
                    int nb = ni >> 1, p = (ni & 1) * 2;
                    MMA_TF32(acc[mi][ni][0], acc[mi][ni][1], acc[mi][ni][2], acc[mi][ni][3],
                             a[mi][0], a[mi][1], a[mi][2], a[mi][3],
                             b2[nb][p], b2[nb][p + 1]);
                }
        }
    }

    const int g4 = lane >> 2, t4 = lane & 3;
#pragma unroll
    for (int mi = 0; mi < 2; ++mi) {
#pragma unroll
        for (int r2 = 0; r2 < 2; ++r2) {
            int row = mBase + wr * 32 + mi * 16 + g4 + r2 * 8;
            float inv = rsum[(long)bh * LL + row];
            float* Cp = ctx + (long)(b * LL + row) * DD + h * HD + wc * 48;
#pragma unroll
            for (int ni = 0; ni < 6; ++ni) {
                int col = ni * 8 + t4 * 2;
                *(float2*)(Cp + col) = make_float2(acc[mi][ni][r2 * 2 + 0] * inv,
                                                   acc[mi][ni][r2 * 2 + 1] * inv);
            }
        }
    }
}

// ---------------- V transpose per head: vT[bh][96][512] ----------------
__global__ void __launch_bounds__(256) vT_kernel(
    const float* __restrict__ qkv, float* __restrict__ vT)
{
    __shared__ float t[32][33];
    const int bh = blockIdx.z, b = bh >> 3, h = bh & 7;
    const int x = blockIdx.x * 32 + threadIdx.x;   // d
    const int y = blockIdx.y * 32 + threadIdx.y;   // k
    const float* src = qkv + (long)(b * LL) * (3 * DD) + 2 * DD + h * HD;
#pragma unroll
    for (int i = 0; i < 32; i += 8)
        t[threadIdx.y + i][threadIdx.x] = src[(long)(y + i) * (3 * DD) + x];
    __syncthreads();
    const int x2 = blockIdx.y * 32 + threadIdx.x;
    const int y2 = blockIdx.x * 32 + threadIdx.y;
    float* dst = vT + (long)bh * HD * LL;
#pragma unroll
    for (int i = 0; i < 32; i += 8)
        dst[(long)(y2 + i) * LL + x2] = t[threadIdx.x][threadIdx.y + i];
}

// ---------------- batched transpose: dst[z][C][R] = src[z][R][C]^T ----------------
__global__ void __launch_bounds__(256) transpose_kernel(
    const float* __restrict__ src, float* __restrict__ dst, int R, int C)
{
    __shared__ float t[32][33];
    long bo = (long)blockIdx.z * R * C;
    int x = blockIdx.x * 32 + threadIdx.x;
    int y = blockIdx.y * 32 + threadIdx.y;
#pragma unroll
    for (int i = 0; i < 32; i += 8)
        t[threadIdx.y + i][threadIdx.x] = src[bo + (long)(y + i) * C + x];
    __syncthreads();
    int x2 = blockIdx.y * 32 + threadIdx.x;
    int y2 = blockIdx.x * 32 + threadIdx.y;
#pragma unroll
    for (int i = 0; i < 32; i += 8)
        dst[bo + (long)(y2 + i) * R + x2] = t[threadIdx.x][threadIdx.y + i];
}

// ---------------- residual add + LayerNorm (in-place on x) ----------------
__global__ void __launch_bounds__(256) add_ln_kernel(
    float* __restrict__ x, const float* __restrict__ delta,
    const float* __restrict__ pos, const float* __restrict__ tok,
    const float* __restrict__ g, const float* __restrict__ bt, int mode)
{
    __shared__ float sh[8];
    int row = blockIdx.x;
    int l = row & (LL - 1);
    int t = threadIdx.x, w = t >> 5, lane = t & 31;
    float* xr = x + (long)row * DD;
    float y[3];
#pragma unroll
    for (int i = 0; i < 3; ++i) {
        int d = t + i * 256;
        float v = xr[d];
        if (mode == 0) v += pos[l * DD + d] + tok[d];
        else           v += delta[(long)row * DD + d];
        y[i] = v;
    }
    float s = y[0] + y[1] + y[2];
#pragma unroll
    for (int o = 16; o; o >>= 1) s += __shfl_xor_sync(0xffffffffu, s, o);
    if (lane == 0) sh[w] = s;
    __syncthreads();
    s = sh[0] + sh[1] + sh[2] + sh[3] + sh[4] + sh[5] + sh[6] + sh[7];
    float mean = s * (1.f / DD);
    __syncthreads();
    float sq = 0.f;
#pragma unroll
    for (int i = 0; i < 3; ++i) { float d2 = y[i] - mean; sq += d2 * d2; }
#pragma unroll
    for (int o = 16; o; o >>= 1) sq += __shfl_xor_sync(0xffffffffu, sq, o);
    if (lane == 0) sh[w] = sq;
    __syncthreads();
    sq = sh[0] + sh[1] + sh[2] + sh[3] + sh[4] + sh[5] + sh[6] + sh[7];
    float rstd = rsqrtf(sq * (1.f / DD) + 1e-12f);
#pragma unroll
    for (int i = 0; i < 3; ++i) {
        int d = t + i * 256;
        xr[d] = (y[i] - mean) * rstd * g[d] + bt[d];
    }
}

// ---------------- assemble x = [queries | gfeat | text] ----------------
__global__ void __launch_bounds__(256) assemble_kernel(
    const float* __restrict__ qtok, const float* __restrict__ gfeat,
    const float* __restrict__ text, float* __restrict__ x)
{
    int row = blockIdx.x;
    int b = row >> 9, l = row & (LL - 1);
    int t = threadIdx.x;
    float* xr = x + (long)row * DD;
#pragma unroll
    for (int i = 0; i < 3; ++i) {
        int d = t + i * 256;
        float v;
        if (l < NQ)        v = qtok[l * DD + d];
        else if (l < TS)   v = gfeat[((long)(b * NN + l - NQ)) * DD + d];
        else               v = text[((long)(b * TT + l - TS)) * DD + d];
        xr[d] = v;
    }
}

// ---------------- output: text slice ----------------
__global__ void __launch_bounds__(256) output_kernel(const float* __restrict__ x,
                                                     float* __restrict__ out)
{
    long i = (long)blockIdx.x * 256 + threadIdx.x;
    const long total = (long)BB * TT * DD;
    if (i >= total) return;
    int d = (int)(i % DD);
    long r = i / DD;
    int tt = (int)(r % TT);
    int b  = (int)(r / TT);
    out[i] = x[((long)(b * LL + TS + tt)) * DD + d];
}

// ---------------- host orchestration ----------------
extern "C" void kernel_launch(void* const* d_in, const int* in_sizes, int n_in,
                              void* d_out, int out_size)
{
    const float* gnf     = (const float*)d_in[0];
    const float* text    = (const float*)d_in[1];
    const int*   ta      = (const int*)  d_in[2];
    const int*   gm      = (const int*)  d_in[3];
    const float* qtok    = (const float*)d_in[4];
    const float* gproj_w = (const float*)d_in[5];
    const float* gproj_b = (const float*)d_in[6];
    const float* pos     = (const float*)d_in[7];
    const float* tok     = (const float*)d_in[8];
    const float* eg      = (const float*)d_in[9];
    const float* eb      = (const float*)d_in[10];
    const float* qkv_w   = (const float*)d_in[11];
    const float* qkv_b   = (const float*)d_in[12];
    const float* ao_w    = (const float*)d_in[13];
    const float* ao_b    = (const float*)d_in[14];
    const float* ln1g    = (const float*)d_in[15];
    const float* ln1b    = (const float*)d_in[16];
    const float* ff1w    = (const float*)d_in[17];
    const float* ff1b    = (const float*)d_in[18];
    const float* ff2w    = (const float*)d_in[19];
    const float* ff2b    = (const float*)d_in[20];
    const float* ln2g    = (const float*)d_in[21];
    const float* ln2b    = (const float*)d_in[22];

    float *x, *qkv, *S, *ctx, *y, *hb, *wT, *vT, *rs;
    cudaGetSymbolAddress((void**)&x,   g_x);
    cudaGetSymbolAddress((void**)&qkv, g_qkv);
    cudaGetSymbolAddress((void**)&S,   g_S);
    cudaGetSymbolAddress((void**)&ctx, g_ctx);
    cudaGetSymbolAddress((void**)&y,   g_y);
    cudaGetSymbolAddress((void**)&hb,  g_h);
    cudaGetSymbolAddress((void**)&wT,  g_wT);
    cudaGetSymbolAddress((void**)&vT,  g_vT);
    cudaGetSymbolAddress((void**)&rs,  g_rsum);

    float* qkvT   = wT + WT_QKV;
    float* aoT    = wT + WT_AO;
    float* ff1T   = wT + WT_FF1;
    float* ff2T   = wT + WT_FF2;
    float* gprojT = wT + WT_GP;

    cudaFuncSetAttribute(tc_gemm, cudaFuncAttributeMaxDynamicSharedMemorySize, GSMEM_BYTES);
    cudaFuncSetAttribute(tc_attn_scores, cudaFuncAttributeMaxDynamicSharedMemorySize, SSMEM_BYTES);
    cudaFuncSetAttribute(tc_attn_ctx, cudaFuncAttributeMaxDynamicSharedMemorySize, CSMEM_BYTES);

    dim3 tb(32, 8);
    // weight transposes into K-major B^T layouts
    transpose_kernel<<<dim3(2304/32, 768/32, 6), tb>>>(qkv_w, qkvT, 768, 2304);
    transpose_kernel<<<dim3(768/32,  768/32, 6), tb>>>(ao_w,  aoT,  768, 768);
    transpose_kernel<<<dim3(3072/32, 768/32, 6), tb>>>(ff1w,  ff1T, 768, 3072);
    transpose_kernel<<<dim3(768/32, 3072/32, 6), tb>>>(ff2w,  ff2T, 3072, 768);
    transpose_kernel<<<dim3(768/32,  768/32, 1), tb>>>(gproj_w, gprojT, 768, 768);

    // graph projection: gfeat(tmp in y) = gnf[2048,768] @ gproj_w + gproj_b
    tc_gemm<<<dim3(DD/128, (BB*NN)/128), 256, GSMEM_BYTES>>>(
        gnf, gprojT, gproj_b, y, BB*NN, DD, DD, 0);
    // assemble x, then embedding LN
    assemble_kernel<<<ROWS, 256>>>(qtok, y, text, x);
    add_ln_kernel<<<ROWS, 256>>>(x, nullptr, pos, tok, eg, eb, 0);

    for (int i = 0; i < NLAY; ++i) {
        tc_gemm<<<dim3((3*DD)/128, ROWS/128), 256, GSMEM_BYTES>>>(
            x, qkvT + (long)i * 2304 * 768, qkv_b + (long)i * 3 * DD, qkv,
            ROWS, 3*DD, DD, 0);
        // attention: fused scores+exp+rowsum, V transpose, P@V * inv
        tc_attn_scores<<<dim3(LL/128, BB*HH), 256, SSMEM_BYTES>>>(qkv, gm, ta, S, rs);
        vT_kernel<<<dim3(HD/32, LL/32, BB*HH), tb>>>(qkv, vT);
        tc_attn_ctx<<<dim3(LL/128, BB*HH), 256, CSMEM_BYTES>>>(S, vT, rs, ctx);
        tc_gemm<<<dim3(DD/128, ROWS/128), 256, GSMEM_BYTES>>>(
            ctx, aoT + (long)i * 768 * 768, ao_b + (long)i * DD, y, ROWS, DD, DD, 0);
        add_ln_kernel<<<ROWS, 256>>>(x, y, nullptr, nullptr,
                                     ln1g + (long)i * DD, ln1b + (long)i * DD, 1);
        tc_gemm<<<dim3(FF/128, ROWS/128), 256, GSMEM_BYTES>>>(
            x, ff1T + (long)i * 3072 * 768, ff1b + (long)i * FF, hb, ROWS, FF, DD, 1);
        tc_gemm<<<dim3(DD/128, ROWS/128), 256, GSMEM_BYTES>>>(
            hb, ff2T + (long)i * 768 * 3072, ff2b + (long)i * DD, y, ROWS, DD, FF, 0);
        add_ln_kernel<<<ROWS, 256>>>(x, y, nullptr, nullptr,
                                     ln2g + (long)i * DD, ln2b + (long)i * DD, 1);
    }

    long total = (long)BB * TT * DD;
    output_kernel<<<(int)((total + 255) / 256), 256>>>(x, (float*)d_out);
}

// round 12
// speedup vs baseline: 5.6348x; 1.8216x over previous
#include <cuda_runtime.h>
#include <cuda_fp16.h>
#include <math.h>
#include <stdint.h>

// ---------------- problem dims ----------------
#define BB   16
#define NQ   32
#define NN   128
#define TT   352
#define DD   768
#define HH   8
#define LL   512
#define HD   96
#define FF   3072
#define NLAY 6
#define ROWS (BB*LL)          // 8192
#define TS   (NQ+NN)          // 160 text start

// ---------------- scratch (static device globals; no allocs) ----------------
__device__ float  g_x[ROWS*DD];            // fp32 activations
__device__ float  g_y[ROWS*DD];            // fp32 gemm output (AO/FF2/gproj)
__device__ float  g_rsum[BB*HH*LL];        // 1/rowsum per (bh,q)
__device__ __half g_x16[ROWS*DD];          // fp16 activations (GEMM A side)
__device__ __half g_qkv16[ROWS*3*DD];      // fp16 qkv
__device__ __half g_S16[BB*HH*LL*LL];      // fp16 unnormalized probs
__device__ __half g_ctx16[ROWS*DD];        // fp16 attn context
__device__ __half g_h16[ROWS*FF];          // fp16 ffn hidden
__device__ __half g_vT16[BB*HH*HD*LL];     // fp16 V^T per head [128][96][512]
__device__ __half g_gnf16[BB*NN*DD];       // fp16 graph node features
// fp16 transposed weights
#define WT_QKV   0L
#define WT_AO    (WT_QKV + 6L*2304*768)
#define WT_FF1   (WT_AO  + 6L*768*768)
#define WT_FF2   (WT_FF1 + 6L*3072*768)
#define WT_GP    (WT_FF2 + 6L*768*3072)
#define WT_TOTAL (WT_GP + 768L*768)
__device__ __half g_w16[WT_TOTAL];

// ================= helpers =================
__device__ __forceinline__ uint32_t smem_u32(const void* p) {
    uint32_t a;
    asm("{ .reg .u64 t; cvta.to.shared.u64 t, %1; cvt.u32.u64 %0, t; }" : "=r"(a) : "l"(p));
    return a;
}
__device__ __forceinline__ uint32_t swz128(uint32_t off) { return off ^ ((off >> 3) & 0x70); }
#define CP_ASYNC16(s, g) \
    asm volatile("cp.async.ca.shared.global [%0], [%1], 16;" :: "r"(s), "l"(g))
#define CP_COMMIT() asm volatile("cp.async.commit_group;" ::: "memory")
#define CP_WAIT1()  asm volatile("cp.async.wait_group 1;" ::: "memory")
#define CP_WAIT0()  asm volatile("cp.async.wait_group 0;" ::: "memory")
#define LDSM_X4(r0, r1, r2, r3, addr) \
    asm volatile("ldmatrix.sync.aligned.m8n8.x4.shared.b16 {%0,%1,%2,%3}, [%4];" \
        : "=r"(r0), "=r"(r1), "=r"(r2), "=r"(r3) : "r"(addr))
// fp16 mma m16n8k16: a0..a3 (k16 x m16), b0,b1 (k16 x n8), fp32 accum
#define MMA_F16(c0, c1, c2, c3, a0, a1, a2, a3, b0, b1) \
    asm volatile("mma.sync.aligned.m16n8k16.row.col.f32.f16.f16.f32 " \
        "{%0,%1,%2,%3}, {%4,%5,%6,%7}, {%8,%9}, {%0,%1,%2,%3};" \
        : "+f"(c0), "+f"(c1), "+f"(c2), "+f"(c3) \
        : "r"(a0), "r"(a1), "r"(a2), "r"(a3), "r"(b0), "r"(b1))

#define GSTAGE 32768                   // A 16KB + B 16KB (128 rows x 64 halves each)
#define GSMEM_BYTES (3 * GSTAGE)
#define SSMEM_BYTES (5 * 16384)        // Q 2 panels + K 3-slot ring
#define CSTAGE 28672                   // A 16KB + B 12KB
#define CSMEM_BYTES (3 * CSTAGE)

// ============ fp16 mma GEMM: C[M,N] = A[M,K] @ Bt[N,K]^T + bias ============
// BM=BN=128, BK=64 halves, 256 threads (2x4 warps), 3-stage cp.async pipeline.
// Output to C32 (fp32) or C16 (fp16), optional exact GELU.
__global__ void __launch_bounds__(256) tc_gemm_h(
    const __half* __restrict__ A, const __half* __restrict__ Bt,
    const float* __restrict__ bias, float* __restrict__ C32,
    __half* __restrict__ C16, int M, int N, int K, int act)
{
    extern __shared__ char smem[];
    const uint32_t sb = smem_u32(smem);
    const int tid = threadIdx.x;
    const int wid = tid >> 5, lane = tid & 31;
    const int wr = wid >> 2, wc = wid & 3;
    const int mBase = blockIdx.y * 128, nBase = blockIdx.x * 128;
    const int KT = K >> 6;

    float acc[4][4][4];
#pragma unroll
    for (int mi = 0; mi < 4; ++mi)
#pragma unroll
        for (int ni = 0; ni < 4; ++ni)
#pragma unroll
            for (int r = 0; r < 4; ++r) acc[mi][ni][r] = 0.f;

#pragma unroll
    for (int s = 0; s < 2; ++s) {
        const long koff = (long)s * 64;
        const uint32_t st = sb + s * GSTAGE;
#pragma unroll
        for (int i = 0; i < 4; ++i) {
            int g = tid + i * 256, row = g >> 3, seg = g & 7;
            uint32_t ds = swz128(row * 128 + seg * 16);
            CP_ASYNC16(st + ds,         A  + (long)(mBase + row) * K + koff + seg * 8);
            CP_ASYNC16(st + 16384 + ds, Bt + (long)(nBase + row) * K + koff + seg * 8);
        }
        CP_COMMIT();
    }

    const int a_row = (lane & 7) + ((lane >> 3) & 1) * 8;
    const int a_seg = ((lane >> 4) & 1) * 16;
    const int b_row = (lane & 7) + ((lane >> 4) & 1) * 8;
    const int b_seg = ((lane >> 3) & 1) * 16;

    for (int j = 0; j < KT; ++j) {
        if (j == KT - 1) { CP_WAIT0(); } else { CP_WAIT1(); }
        __syncthreads();
        if (j + 2 < KT) {
            const long koff = (long)(j + 2) * 64;
            const uint32_t st = sb + ((j + 2) % 3) * GSTAGE;
#pragma unroll
            for (int i = 0; i < 4; ++i) {
                int g = tid + i * 256, row = g >> 3, seg = g & 7;
                uint32_t ds = swz128(row * 128 + seg * 16);
                CP_ASYNC16(st + ds,         A  + (long)(mBase + row) * K + koff + seg * 8);
                CP_ASYNC16(st + 16384 + ds, Bt + (long)(nBase + row) * K + koff + seg * 8);
            }
            CP_COMMIT();
        }
        const uint32_t As = sb + (j % 3) * GSTAGE;
        const uint32_t Bs = As + 16384;
#pragma unroll
        for (int kk = 0; kk < 4; ++kk) {         // 4 x k16
            uint32_t a[4][4], b[2][4];
#pragma unroll
            for (int mi = 0; mi < 4; ++mi) {
                int row = wr * 64 + mi * 16 + a_row;
                LDSM_X4(a[mi][0], a[mi][1], a[mi][2], a[mi][3],
                        As + swz128(row * 128 + kk * 32 + a_seg));
            }
#pragma unroll
            for (int nb = 0; nb < 2; ++nb) {
                int row = wc * 32 + nb * 16 + b_row;
                LDSM_X4(b[nb][0], b[nb][1], b[nb][2], b[nb][3],
                        Bs + swz128(row * 128 + kk * 32 + b_seg));
            }
#pragma unroll
            for (int mi = 0; mi < 4; ++mi)
#pragma unroll
                for (int ni = 0; ni < 4; ++ni) {
                    int nb = ni >> 1, p = (ni & 1) * 2;
                    MMA_F16(acc[mi][ni][0], acc[mi][ni][1], acc[mi][ni][2], acc[mi][ni][3],
                            a[mi][0], a[mi][1], a[mi][2], a[mi][3],
                            b[nb][p], b[nb][p + 1]);
                }
        }
    }

    const int g4 = lane >> 2, t4 = lane & 3;
#pragma unroll
    for (int mi = 0; mi < 4; ++mi) {
#pragma unroll
        for (int r2 = 0; r2 < 2; ++r2) {
            int row = mBase + wr * 64 + mi * 16 + g4 + r2 * 8;
            const float* bp = bias + nBase + wc * 32;
#pragma unroll
            for (int ni = 0; ni < 4; ++ni) {
                int col = ni * 8 + t4 * 2;
                float v0 = acc[mi][ni][r2 * 2 + 0] + bp[col];
                float v1 = acc[mi][ni][r2 * 2 + 1] + bp[col + 1];
                if (act == 1) {
                    v0 = 0.5f * v0 * (1.0f + erff(v0 * 0.70710678118654752f));
                    v1 = 0.5f * v1 * (1.0f + erff(v1 * 0.70710678118654752f));
                }
                if (C16) {
                    *(__half2*)(C16 + (long)row * N + nBase + wc * 32 + col) =
                        __floats2half2_rn(v0, v1);
                } else {
                    *(float2*)(C32 + (long)row * N + nBase + wc * 32 + col) =
                        make_float2(v0, v1);
                }
            }
        }
    }
}

// ---------------- mask helper ----------------
__device__ __forceinline__ int keep_fn(int b, int l, const int* __restrict__ gm,
                                       const int* __restrict__ ta) {
    if (l < NQ) return 1;
    if (l < TS) return gm[b * NN + l - NQ];
    return ta[b * TT + l - TS];
}

// ============ fused scores + exp (fp16): P16 = exp(scale*Q@K^T masked), rsum = 1/rowsum ============
// grid (4 qtiles, 128 bh), 256 threads. Q resident (2 panels: k0-63, k64-95),
// K sub-tiles (2 per key tile) in a 3-slot ring; max-free softmax.
__global__ void __launch_bounds__(256) tc_attn_scores_h(
    const __half* __restrict__ qkv, const int* __restrict__ gm,
    const int* __restrict__ ta, __half* __restrict__ S, float* __restrict__ rsum)
{
    extern __shared__ char smem[];
    const uint32_t sb = smem_u32(smem);
    const int tid = threadIdx.x;
    const int wid = tid >> 5, lane = tid & 31;
    const int wr = wid >> 2, wc = wid & 3;
    const int bh = blockIdx.y, b = bh >> 3, h = bh & 7;
    const int mBase = blockIdx.x * 128;
    const int QS = 3 * DD;   // qkv row stride in halves

    const __half* Aq  = qkv + (long)(b * LL + mBase) * QS + h * HD;
    const __half* Bk0 = qkv + (long)(b * LL) * QS + DD + h * HD;

    // Q panel 0: k0-63 (full 128B rows)
#pragma unroll
    for (int i = 0; i < 4; ++i) {
        int g = tid + i * 256, row = g >> 3, seg = g & 7;
        CP_ASYNC16(sb + swz128(row * 128 + seg * 16), Aq + (long)row * QS + seg * 8);
    }
    // Q panel 1: k64-95 (segs 0-3)
#pragma unroll
    for (int i = 0; i < 2; ++i) {
        int g = tid + i * 256, row = g >> 2, seg = g & 3;
        CP_ASYNC16(sb + 16384 + swz128(row * 128 + seg * 16),
                   Aq + (long)row * QS + 64 + seg * 8);
    }
    CP_COMMIT();
    // K sub-tiles t=0,1 (t = nt*2 + kp)
#pragma unroll
    for (int t = 0; t < 2; ++t) {
        int nt = t >> 1, kp = t & 1;
        uint32_t st = sb + 32768 + (t % 3) * 16384;
        if (kp == 0) {
#pragma unroll
            for (int i = 0; i < 4; ++i) {
                int g = tid + i * 256, row = g >> 3, seg = g & 7;
                CP_ASYNC16(st + swz128(row * 128 + seg * 16),
                           Bk0 + (long)(nt * 128 + row) * QS + seg * 8);
            }
        } else {
#pragma unroll
            for (int i = 0; i < 2; ++i) {
                int g = tid + i * 256, row = g >> 2, seg = g & 3;
                CP_ASYNC16(st + swz128(row * 128 + seg * 16),
                           Bk0 + (long)(nt * 128 + row) * QS + 64 + seg * 8);
            }
        }
        CP_COMMIT();
    }

    const int a_row = (lane & 7) + ((lane >> 3) & 1) * 8;
    const int a_seg = ((lane >> 4) & 1) * 16;
    const int b_row = (lane & 7) + ((lane >> 4) & 1) * 8;
    const int b_seg = ((lane >> 3) & 1) * 16;
    const int g4 = lane >> 2, t4 = lane & 3;
    const float scale = 0.10206207261596577f;  // 1/sqrt(96)

    float acc[4][4][4];
#pragma unroll
    for (int mi = 0; mi < 4; ++mi)
#pragma unroll
        for (int ni = 0; ni < 4; ++ni)
#pragma unroll
            for (int r = 0; r < 4; ++r) acc[mi][ni][r] = 0.f;
    float rowsum[4][2];
#pragma unroll
    for (int mi = 0; mi < 4; ++mi) { rowsum[mi][0] = 0.f; rowsum[mi][1] = 0.f; }

    for (int t = 0; t < 8; ++t) {
        if (t == 7) { CP_WAIT0(); } else { CP_WAIT1(); }
        __syncthreads();
        if (t + 2 < 8) {
            int tn = t + 2, nt = tn >> 1, kp = tn & 1;
            uint32_t st = sb + 32768 + (tn % 3) * 16384;
            if (kp == 0) {
#pragma unroll
                for (int i = 0; i < 4; ++i) {
                    int g = tid + i * 256, row = g >> 3, seg = g & 7;
                    CP_ASYNC16(st + swz128(row * 128 + seg * 16),
                               Bk0 + (long)(nt * 128 + row) * QS + seg * 8);
                }
            } else {
#pragma unroll
                for (int i = 0; i < 2; ++i) {
                    int g = tid + i * 256, row = g >> 2, seg = g & 3;
                    CP_ASYNC16(st + swz128(row * 128 + seg * 16),
                               Bk0 + (long)(nt * 128 + row) * QS + 64 + seg * 8);
                }
            }
            CP_COMMIT();
        }
        const int kp = t & 1;
        const int nkk = kp ? 2 : 4;
        const uint32_t As = sb + kp * 16384;
        const uint32_t Bs = sb + 32768 + (t % 3) * 16384;
        for (int kk = 0; kk < nkk; ++kk) {
            uint32_t a[4][4], b2[2][4];
#pragma unroll
            for (int mi = 0; mi < 4; ++mi) {
                int row = wr * 64 + mi * 16 + a_row;
                LDSM_X4(a[mi][0], a[mi][1], a[mi][2], a[mi][3],
                        As + swz128(row * 128 + kk * 32 + a_seg));
            }
#pragma unroll
            for (int nb = 0; nb < 2; ++nb) {
                int row = wc * 32 + nb * 16 + b_row;
                LDSM_X4(b2[nb][0], b2[nb][1], b2[nb][2], b2[nb][3],
                        Bs + swz128(row * 128 + kk * 32 + b_seg));
            }
#pragma unroll
            for (int mi = 0; mi < 4; ++mi)
#pragma unroll
                for (int ni = 0; ni < 4; ++ni) {
                    int nb = ni >> 1, p = (ni & 1) * 2;
                    MMA_F16(acc[mi][ni][0], acc[mi][ni][1], acc[mi][ni][2], acc[mi][ni][3],
                            a[mi][0], a[mi][1], a[mi][2], a[mi][3],
                            b2[nb][p], b2[nb][p + 1]);
                }
        }

        if (t & 1) {
            const int nBase = (t >> 1) * 128;
#pragma unroll
            for (int mi = 0; mi < 4; ++mi) {
#pragma unroll
                for (int r2 = 0; r2 < 2; ++r2) {
                    int q = mBase + wr * 64 + mi * 16 + g4 + r2 * 8;
                    int kq = keep_fn(b, q, gm, ta);
                    bool qt = q >= TS;
                    __half* Sp = S + ((long)bh * LL + q) * LL;
                    float part = 0.f;
#pragma unroll
                    for (int ni = 0; ni < 4; ++ni) {
                        int col0 = nBase + wc * 32 + ni * 8 + t4 * 2;
                        float v[2];
#pragma unroll
                        for (int e = 0; e < 2; ++e) {
                            int k = col0 + e;
                            int kk2 = keep_fn(b, k, gm, ta);
                            bool kt = k >= TS;
                            bool ok = (kq != 0) && (kk2 != 0);
                            if (qt && kt) ok = ok && (q >= k);
                            if (!qt && kt) ok = false;
                            v[e] = ok ? __expf(acc[mi][ni][r2 * 2 + e] * scale) : 0.f;
                        }
                        part += v[0] + v[1];
                        *(__half2*)(Sp + col0) = __floats2half2_rn(v[0], v[1]);
                    }
                    rowsum[mi][r2] += part;
#pragma unroll
                    for (int ni = 0; ni < 4; ++ni) {
                        acc[mi][ni][r2 * 2 + 0] = 0.f;
                        acc[mi][ni][r2 * 2 + 1] = 0.f;
                    }
                }
            }
        }
    }

    __syncthreads();
    float* ssum = (float*)smem;   // [128][4]
#pragma unroll
    for (int mi = 0; mi < 4; ++mi)
#pragma unroll
        for (int r2 = 0; r2 < 2; ++r2) {
            float v = rowsum[mi][r2];
            v += __shfl_xor_sync(0xffffffffu, v, 1);
            v += __shfl_xor_sync(0xffffffffu, v, 2);
            if (t4 == 0) ssum[(wr * 64 + mi * 16 + g4 + r2 * 8) * 4 + wc] = v;
        }
    __syncthreads();
    if (tid < 128) {
        float tot = ssum[tid * 4] + ssum[tid * 4 + 1] + ssum[tid * 4 + 2] + ssum[tid * 4 + 3];
        rsum[(long)bh * LL + mBase + tid] = 1.f / tot;
    }
}

// ============ ctx16 = (P16 @ V) * inv_rowsum: BM=128, BN=96, K=512 halves ============
// grid: (4 qtile, 128 bh), 256 threads, warp grid 4x2 (32q x 48d), 3-stage.
__global__ void __launch_bounds__(256) tc_attn_ctx_h(
    const __half* __restrict__ S, const __half* __restrict__ vT,
    const float* __restrict__ rsum, __half* __restrict__ ctx)
{
    extern __shared__ char smem[];
    const uint32_t sb = smem_u32(smem);
    const int tid = threadIdx.x;
    const int wid = tid >> 5, lane = tid & 31;
    const int wr = wid >> 1, wc = wid & 1;
    const int bh = blockIdx.y, b = bh >> 3, h = bh & 7;
    const int mBase = blockIdx.x * 128;

    const __half* Ap = S  + ((long)bh * LL + mBase) * LL;
    const __half* Bp = vT + (long)bh * HD * LL;

    float acc[2][6][4];
#pragma unroll
    for (int mi = 0; mi < 2; ++mi)
#pragma unroll
        for (int ni = 0; ni < 6; ++ni)
#pragma unroll
            for (int r = 0; r < 4; ++r) acc[mi][ni][r] = 0.f;

#pragma unroll
    for (int s = 0; s < 2; ++s) {
        const long koff = (long)s * 64;
        const uint32_t st = sb + s * CSTAGE;
#pragma unroll
        for (int i = 0; i < 4; ++i) {
            int g = tid + i * 256, row = g >> 3, seg = g & 7;
            CP_ASYNC16(st + swz128(row * 128 + seg * 16), Ap + (long)row * LL + koff + seg * 8);
        }
#pragma unroll
        for (int i = 0; i < 3; ++i) {
            int g = tid + i * 256, row = g >> 3, seg = g & 7;
            CP_ASYNC16(st + 16384 + swz128(row * 128 + seg * 16),
                       Bp + (long)row * LL + koff + seg * 8);
        }
        CP_COMMIT();
    }

    const int a_row = (lane & 7) + ((lane >> 3) & 1) * 8;
    const int a_seg = ((lane >> 4) & 1) * 16;
    const int b_row = (lane & 7) + ((lane >> 4) & 1) * 8;
    const int b_seg = ((lane >> 3) & 1) * 16;

    for (int j = 0; j < 8; ++j) {
        if (j == 7) { CP_WAIT0(); } else { CP_WAIT1(); }
        __syncthreads();
        if (j + 2 < 8) {
            const long koff = (long)(j + 2) * 64;
            const uint32_t st = sb + ((j + 2) % 3) * CSTAGE;
#pragma unroll
            for (int i = 0; i < 4; ++i) {
                int g = tid + i * 256, row = g >> 3, seg = g & 7;
                CP_ASYNC16(st + swz128(row * 128 + seg * 16),
                           Ap + (long)row * LL + koff + seg * 8);
            }
#pragma unroll
            for (int i = 0; i < 3; ++i) {
                int g = tid + i * 256, row = g >> 3, seg = g & 7;
                CP_ASYNC16(st + 16384 + swz128(row * 128 + seg * 16),
                           Bp + (long)row * LL + koff + seg * 8);
            }
            CP_COMMIT();
        }
        const uint32_t As = sb + (j % 3) * CSTAGE;
        const uint32_t Bs = As + 16384;
#pragma unroll
        for (int kk = 0; kk < 4; ++kk) {
            uint32_t a[2][4], b2[3][4];
#pragma unroll
            for (int mi = 0; mi < 2; ++mi) {
                int row = wr * 32 + mi * 16 + a_row;
                LDSM_X4(a[mi][0], a[mi][1], a[mi][2], a[mi][3],
                        As + swz128(row * 128 + kk * 32 + a_seg));
            }
#pragma unroll
            for (int nb = 0; nb < 3; ++nb) {
                int row = wc * 48 + nb * 16 + b_row;
                LDSM_X4(b2[nb][0], b2[nb][1], b2[nb][2], b2[nb][3],
                        Bs + swz128(row * 128 + kk * 32 + b_seg));
            }
#pragma unroll
            for (int mi = 0; mi < 2; ++mi)
#pragma unroll
                for (int ni = 0; ni < 6; ++ni) {
                    int nb = ni >> 1, p = (ni & 1) * 2;
                    MMA_F16(acc[mi][ni][0], acc[mi][ni][1], acc[mi][ni][2], acc[mi][ni][3],
                            a[mi][0], a[mi][1], a[mi][2], a[mi][3],
                            b2[nb][p], b2[nb][p + 1]);
                }
        }
    }

    const int g4 = lane >> 2, t4 = lane & 3;
#pragma unroll
    for (int mi = 0; mi < 2; ++mi) {
#pragma unroll
        for (int r2 = 0; r2 < 2; ++r2) {
            int row = mBase + wr * 32 + mi * 16 + g4 + r2 * 8;
            float inv = rsum[(long)bh * LL + row];
            __half* Cp = ctx + (long)(b * LL + row) * DD + h * HD + wc * 48;
#pragma unroll
            for (int ni = 0; ni < 6; ++ni) {
                int col = ni * 8 + t4 * 2;
                *(__half2*)(Cp + col) = __floats2half2_rn(acc[mi][ni][r2 * 2 + 0] * inv,
                                                          acc[mi][ni][r2 * 2 + 1] * inv);
            }
        }
    }
}

// ---------------- V transpose per head (fp16): vT[bh][96][512] ----------------
__global__ void __launch_bounds__(256) vT_kernel_h(
    const __half* __restrict__ qkv, __half* __restrict__ vT)
{
    __shared__ __half t[32][34];
    const int bh = blockIdx.z, b = bh >> 3, h = bh & 7;
    const int x = blockIdx.x * 32 + threadIdx.x;   // d
    const int y = blockIdx.y * 32 + threadIdx.y;   // k
    const __half* src = qkv + (long)(b * LL) * (3 * DD) + 2 * DD + h * HD;
#pragma unroll
    for (int i = 0; i < 32; i += 8)
        t[threadIdx.y + i][threadIdx.x] = src[(long)(y + i) * (3 * DD) + x];
    __syncthreads();
    const int x2 = blockIdx.y * 32 + threadIdx.x;  // k
    const int y2 = blockIdx.x * 32 + threadIdx.y;  // d
    __half* dst = vT + (long)bh * HD * LL;
#pragma unroll
    for (int i = 0; i < 32; i += 8)
        dst[(long)(y2 + i) * LL + x2] = t[threadIdx.x][threadIdx.y + i];
}

// ---------------- batched transpose to fp16: dst[z][C][R] = half(src[z][R][C]^T) ----------------
__global__ void __launch_bounds__(256) transpose_h_kernel(
    const float* __restrict__ src, __half* __restrict__ dst, int R, int C)
{
    __shared__ float t[32][33];
    long bo = (long)blockIdx.z * R * C;
    int x = blockIdx.x * 32 + threadIdx.x;
    int y = blockIdx.y * 32 + threadIdx.y;
#pragma unroll
    for (int i = 0; i < 32; i += 8)
        t[threadIdx.y + i][threadIdx.x] = src[bo + (long)(y + i) * C + x];
    __syncthreads();
    int x2 = blockIdx.y * 32 + threadIdx.x;
    int y2 = blockIdx.x * 32 + threadIdx.y;
#pragma unroll
    for (int i = 0; i < 32; i += 8)
        dst[bo + (long)(y2 + i) * R + x2] = __float2half(t[threadIdx.x][threadIdx.y + i]);
}

// ---------------- fp32 -> fp16 elementwise ----------------
__global__ void __launch_bounds__(256) conv16_kernel(
    const float* __restrict__ in, __half* __restrict__ out, long n)
{
    long i = (long)blockIdx.x * 256 + threadIdx.x;
    if (i < n) out[i] = __float2half(in[i]);
}

// ---------------- residual add + LayerNorm (fp32 x + fp16 x16 out) ----------------
__global__ void __launch_bounds__(256) add_ln_kernel(
    float* __restrict__ x, __half* __restrict__ x16, const float* __restrict__ delta,
    const float* __restrict__ pos, const float* __restrict__ tok,
    const float* __restrict__ g, const float* __restrict__ bt, int mode)
{
    __shared__ float sh[8];
    int row = blockIdx.x;
    int l = row & (LL - 1);
    int t = threadIdx.x, w = t >> 5, lane = t & 31;
    float* xr = x + (long)row * DD;
    float y[3];
#pragma unroll
    for (int i = 0; i < 3; ++i) {
        int d = t + i * 256;
        float v = xr[d];
        if (mode == 0) v += pos[l * DD + d] + tok[d];
        else           v += delta[(long)row * DD + d];
        y[i] = v;
    }
    float s = y[0] + y[1] + y[2];
#pragma unroll
    for (int o = 16; o; o >>= 1) s += __shfl_xor_sync(0xffffffffu, s, o);
    if (lane == 0) sh[w] = s;
    __syncthreads();
    s = sh[0] + sh[1] + sh[2] + sh[3] + sh[4] + sh[5] + sh[6] + sh[7];
    float mean = s * (1.f / DD);
    __syncthreads();
    float sq = 0.f;
#pragma unroll
    for (int i = 0; i < 3; ++i) { float d2 = y[i] - mean; sq += d2 * d2; }
#pragma unroll
    for (int o = 16; o; o >>= 1) sq += __shfl_xor_sync(0xffffffffu, sq, o);
    if (lane == 0) sh[w] = sq;
    __syncthreads();
    sq = sh[0] + sh[1] + sh[2] + sh[3] + sh[4] + sh[5] + sh[6] + sh[7];
    float rstd = rsqrtf(sq * (1.f / DD) + 1e-12f);
#pragma unroll
    for (int i = 0; i < 3; ++i) {
        int d = t + i * 256;
        float o = (y[i] - mean) * rstd * g[d] + bt[d];
        xr[d] = o;
        x16[(long)row * DD + d] = __float2half(o);
    }
}

// ---------------- assemble x = [queries | gfeat | text] ----------------
__global__ void __launch_bounds__(256) assemble_kernel(
    const float* __restrict__ qtok, const float* __restrict__ gfeat,
    const float* __restrict__ text, float* __restrict__ x)
{
    int row = blockIdx.x;
    int b = row >> 9, l = row & (LL - 1);
    int t = threadIdx.x;
    float* xr = x + (long)row * DD;
#pragma unroll
    for (int i = 0; i < 3; ++i) {
        int d = t + i * 256;
        float v;
        if (l < NQ)        v = qtok[l * DD + d];
        else if (l < TS)   v = gfeat[((long)(b * NN + l - NQ)) * DD + d];
        else               v = text[((long)(b * TT + l - TS)) * DD + d];
        xr[d] = v;
    }
}

// ---------------- output: text slice ----------------
__global__ void __launch_bounds__(256) output_kernel(const float* __restrict__ x,
                                                     float* __restrict__ out)
{
    long i = (long)blockIdx.x * 256 + threadIdx.x;
    const long total = (long)BB * TT * DD;
    if (i >= total) return;
    int d = (int)(i % DD);
    long r = i / DD;
    int tt = (int)(r % TT);
    int b  = (int)(r / TT);
    out[i] = x[((long)(b * LL + TS + tt)) * DD + d];
}

// ---------------- host orchestration ----------------
extern "C" void kernel_launch(void* const* d_in, const int* in_sizes, int n_in,
                              void* d_out, int out_size)
{
    const float* gnf     = (const float*)d_in[0];
    const float* text    = (const float*)d_in[1];
    const int*   ta      = (const int*)  d_in[2];
    const int*   gm      = (const int*)  d_in[3];
    const float* qtok    = (const float*)d_in[4];
    const float* gproj_w = (const float*)d_in[5];
    const float* gproj_b = (const float*)d_in[6];
    const float* pos     = (const float*)d_in[7];
    const float* tok     = (const float*)d_in[8];
    const float* eg      = (const float*)d_in[9];
    const float* eb      = (const float*)d_in[10];
    const float* qkv_w   = (const float*)d_in[11];
    const float* qkv_b   = (const float*)d_in[12];
    const float* ao_w    = (const float*)d_in[13];
    const float* ao_b    = (const float*)d_in[14];
    const float* ln1g    = (const float*)d_in[15];
    const float* ln1b    = (const float*)d_in[16];
    const float* ff1w    = (const float*)d_in[17];
    const float* ff1b    = (const float*)d_in[18];
    const float* ff2w    = (const float*)d_in[19];
    const float* ff2b    = (const float*)d_in[20];
    const float* ln2g    = (const float*)d_in[21];
    const float* ln2b    = (const float*)d_in[22];

    float *x, *y, *rs;
    __half *x16, *qkv16, *S16, *ctx16, *h16, *vT16, *gnf16, *w16;
    cudaGetSymbolAddress((void**)&x,     g_x);
    cudaGetSymbolAddress((void**)&y,     g_y);
    cudaGetSymbolAddress((void**)&rs,    g_rsum);
    cudaGetSymbolAddress((void**)&x16,   g_x16);
    cudaGetSymbolAddress((void**)&qkv16, g_qkv16);
    cudaGetSymbolAddress((void**)&S16,   g_S16);
    cudaGetSymbolAddress((void**)&ctx16, g_ctx16);
    cudaGetSymbolAddress((void**)&h16,   g_h16);
    cudaGetSymbolAddress((void**)&vT16,  g_vT16);
    cudaGetSymbolAddress((void**)&gnf16, g_gnf16);
    cudaGetSymbolAddress((void**)&w16,   g_w16);

    __half* qkvT   = w16 + WT_QKV;
    __half* aoT    = w16 + WT_AO;
    __half* ff1T   = w16 + WT_FF1;
    __half* ff2T   = w16 + WT_FF2;
    __half* gprojT = w16 + WT_GP;

    cudaFuncSetAttribute(tc_gemm_h, cudaFuncAttributeMaxDynamicSharedMemorySize, GSMEM_BYTES);
    cudaFuncSetAttribute(tc_attn_scores_h, cudaFuncAttributeMaxDynamicSharedMemorySize, SSMEM_BYTES);
    cudaFuncSetAttribute(tc_attn_ctx_h, cudaFuncAttributeMaxDynamicSharedMemorySize, CSMEM_BYTES);

    dim3 tb(32, 8);
    // weight transposes into K-major fp16 B^T layouts
    transpose_h_kernel<<<dim3(2304/32, 768/32, 6), tb>>>(qkv_w, qkvT, 768, 2304);
    transpose_h_kernel<<<dim3(768/32,  768/32, 6), tb>>>(ao_w,  aoT,  768, 768);
    transpose_h_kernel<<<dim3(3072/32, 768/32, 6), tb>>>(ff1w,  ff1T, 768, 3072);
    transpose_h_kernel<<<dim3(768/32, 3072/32, 6), tb>>>(ff2w,  ff2T, 3072, 768);
    transpose_h_kernel<<<dim3(768/32,  768/32, 1), tb>>>(gproj_w, gprojT, 768, 768);
    conv16_kernel<<<(int)(((long)BB*NN*DD + 255) / 256), 256>>>(gnf, gnf16, (long)BB*NN*DD);

    // graph projection (fp32 out into y)
    tc_gemm_h<<<dim3(DD/128, (BB*NN)/128), 256, GSMEM_BYTES>>>(
        gnf16, gprojT, gproj_b, y, nullptr, BB*NN, DD, DD, 0);
    assemble_kernel<<<ROWS, 256>>>(qtok, y, text, x);
    add_ln_kernel<<<ROWS, 256>>>(x, x16, nullptr, pos, tok, eg, eb, 0);

    for (int i = 0; i < NLAY; ++i) {
        tc_gemm_h<<<dim3((3*DD)/128, ROWS/128), 256, GSMEM_BYTES>>>(
            x16, qkvT + (long)i * 2304 * 768, qkv_b + (long)i * 3 * DD,
            nullptr, qkv16, ROWS, 3*DD, DD, 0);
        tc_attn_scores_h<<<dim3(LL/128, BB*HH), 256, SSMEM_BYTES>>>(qkv16, gm, ta, S16, rs);
        vT_kernel_h<<<dim3(HD/32, LL/32, BB*HH), tb>>>(qkv16, vT16);
        tc_attn_ctx_h<<<dim3(LL/128, BB*HH), 256, CSMEM_BYTES>>>(S16, vT16, rs, ctx16);
        tc_gemm_h<<<dim3(DD/128, ROWS/128), 256, GSMEM_BYTES>>>(
            ctx16, aoT + (long)i * 768 * 768, ao_b + (long)i * DD,
            y, nullptr, ROWS, DD, DD, 0);
        add_ln_kernel<<<ROWS, 256>>>(x, x16, y, nullptr, nullptr,
                                     ln1g + (long)i * DD, ln1b + (long)i * DD, 1);
        tc_gemm_h<<<dim3(FF/128, ROWS/128), 256, GSMEM_BYTES>>>(
            x16, ff1T + (long)i * 3072 * 768, ff1b + (long)i * FF,
            nullptr, h16, ROWS, FF, DD, 1);
        tc_gemm_h<<<dim3(DD/128, ROWS/128), 256, GSMEM_BYTES>>>(
            h16, ff2T + (long)i * 768 * 3072, ff2b + (long)i * DD,
            y, nullptr, ROWS, DD, FF, 0);
        add_ln_kernel<<<ROWS, 256>>>(x, x16, y, nullptr, nullptr,
                                     ln2g + (long)i * DD, ln2b + (long)i * DD, 1);
    }

    long total = (long)BB * TT * DD;
    output_kernel<<<(int)((total + 255) / 256), 256>>>(x, (float*)d_out);
}